// round 12
// baseline (speedup 1.0000x reference)
#include <cuda_runtime.h>
#include <math.h>
#include <float.h>

#define NIMG   16
#define KSEL   1000
#define NCAND  3000
#define NPICK  100
#define HWTOT  13125
#define HWPAD  13128
#define MTOT   1050000
#define CAP    262144

// Output layout (float32, concatenated tuple: boxes, scores, classes, keep)
#define OFS_BOX 0
#define OFS_SC  (NIMG*NPICK*4)
#define OFS_CL  (OFS_SC + NIMG*NPICK)
#define OFS_KP  (OFS_CL + NIMG*NPICK)

// ---------------- scratch (device globals, no allocation) ----------------
__device__ float    g_t[NIMG*HWPAD];      // sigmoid(ctr) per location
__device__ float    g_xc0[NIMG*HWPAD];    // static cutoff: x >= xc0 => key may be >= 0.5
__device__ unsigned g_h2[NIMG*3*2048];    // fallback coarse hist
__device__ unsigned g_F[NIMG*3];
__device__ unsigned g_fb[NIMG*3];
__device__ unsigned g_colcnt[NIMG*3];
__device__ unsigned g_colkey[(size_t)NIMG*3*CAP];
__device__ unsigned g_colpos[(size_t)NIMG*3*CAP];
__device__ float4   g_cbox[NIMG*NCAND];
__device__ float    g_csc[NIMG*NCAND];
__device__ int      g_ccls[NIMG*NCAND];

__device__ __forceinline__ float fsigm(float x) { return __fdividef(1.0f, 1.0f + __expf(-x)); }

// Conservative x-cutoff: any element whose exact key (= fl(fsigm(x)*t)) can be
// >= Fv satisfies x >= cutval(Fv,t).
__device__ __forceinline__ float cutval(float Fv, float t)
{
    if (!(t > Fv)) return (t == Fv) ? 16.0f : FLT_MAX;
    float r = Fv / (t - Fv);
    if (r > 1.0e6f) return -1000.0f;
    return logf(r) - (0.05f + 5e-6f * r);
}

// ---------------- init: tables + zero scratch ----------------
__global__ void init_kernel(const float* __restrict__ c0, const float* __restrict__ c1,
                            const float* __restrict__ c2)
{
    int i0 = blockIdx.x * blockDim.x + threadIdx.x;
    int st = gridDim.x * blockDim.x;
    for (int j = i0; j < NIMG*3*2048; j += st) g_h2[j] = 0;
    for (int j = i0; j < NIMG*3; j += st) { g_colcnt[j] = 0; g_fb[j] = 0; }
    for (int j = i0; j < NIMG*NCAND; j += st) {
        g_csc[j] = -1.0f; g_ccls[j] = 0;
        g_cbox[j] = make_float4(0.f, 0.f, 0.f, 0.f);
    }
    for (int j = i0; j < NIMG*HWPAD; j += st) {
        int n = j / HWPAD, r = j - n * HWPAD;
        float t = 0.0f;
        if (r < 10000)      t = fsigm(c0[n*10000 + r]);
        else if (r < 12500) t = fsigm(c1[n*2500  + (r - 10000)]);
        else if (r < HWTOT) t = fsigm(c2[n*625   + (r - 12500)]);
        g_t[j]   = t;
        g_xc0[j] = cutval(0.5f, t);
    }
}

// ---------------- the single big scan: filter + exact append of keys >= 0.5 ----------
template<int HW, bool VEC>
__device__ __forceinline__ void scan_body(int e, float4 xv, const float* __restrict__ tb,
                                          const float* __restrict__ cb, int seg, unsigned lane)
{
    float xs[4] = {xv.x, xv.y, xv.z, xv.w};
    float cs[4];
    int hwb = 0;
    if (VEC) {
        int c = e / HW; hwb = e - c*HW;
        float4 cv = *reinterpret_cast<const float4*>(cb + hwb);
        cs[0] = cv.x; cs[1] = cv.y; cs[2] = cv.z; cs[3] = cv.w;
    }
    #pragma unroll
    for (int j = 0; j < 4; ++j) {
        bool take = false; unsigned key = 0;
        int hw;
        if (VEC) hw = hwb + j;
        else { int e2 = e + j; int c = e2 / HW; hw = e2 - c*HW; }
        float cut = VEC ? cs[j] : cb[hw];
        if (xs[j] >= cut) {
            float s = fsigm(xs[j]);
            key = __float_as_uint(s * tb[hw]);
            take = key >= 0x3F000000u;     // exact: score >= 0.5
        }
        unsigned mask = __activemask();
        unsigned bal = __ballot_sync(mask, take);
        if (take) {
            int leader = __ffs(bal) - 1;
            unsigned rank = __popc(bal & ((1u << lane) - 1u));
            unsigned basep = 0;
            if ((int)lane == leader)
                basep = atomicAdd(&g_colcnt[seg], (unsigned)__popc(bal));
            basep = __shfl_sync(bal, basep, leader);
            unsigned idx = basep + rank;
            if (idx < CAP) {
                g_colkey[(size_t)seg*CAP + idx] = key;
                g_colpos[(size_t)seg*CAP + idx] = (unsigned)(e + j);
            }
        }
    }
}

__global__ __launch_bounds__(256) void scan_kernel(
    const float* __restrict__ c0, const float* __restrict__ c1, const float* __restrict__ c2)
{
    int n = blockIdx.y, bx = blockIdx.x;
    int lev, b0, nb, vlo, vhi, ctro;
    const float* src;
    if (bx < 48)      { lev = 0; b0 = 0;  nb = 48; vlo = 0;      vhi = 200000; ctro = 0;
                        src = c0 + (size_t)n*800000; }
    else if (bx < 60) { lev = 1; b0 = 48; nb = 12; vlo = 200000; vhi = 250000; ctro = 10000;
                        src = c1 + (size_t)n*200000; }
    else              { lev = 2; b0 = 60; nb = 4;  vlo = 250000; vhi = 262500; ctro = 12500;
                        src = c2 + (size_t)n*50000; }
    int seg = n*3 + lev;
    const float* tb = g_t   + n*HWPAD + ctro;
    const float* cb = g_xc0 + n*HWPAD + ctro;
    int vstride = nb * blockDim.x;
    int base = vlo * 4;
    unsigned lane = threadIdx.x & 31;

    for (int v = vlo + (bx - b0)*blockDim.x + threadIdx.x; v < vhi; v += vstride) {
        int e = v*4 - base;
        float4 xv = *reinterpret_cast<const float4*>(src + e);
        if (lev == 0)      scan_body<10000, true>(e, xv, tb, cb, seg, lane);
        else if (lev == 1) scan_body<2500, true>(e, xv, tb, cb, seg, lane);
        else               scan_body<625, false>(e, xv, tb, cb, seg, lane);
    }
}

// ---------------- block-level histogram select (descending) ----------------
__device__ __forceinline__ void bsel(unsigned* sh, int nb, unsigned target,
                                     int* r_bin, unsigned* r_krem)
{
    __shared__ unsigned gsum[64];
    int tid = threadIdx.x;
    int ngroups = nb / 32;
    if (tid < ngroups) {
        unsigned s = 0;
        for (int j = 0; j < 32; ++j) s += sh[tid*32 + j];
        gsum[tid] = s;
    }
    __syncthreads();
    if (tid == 0) {
        unsigned cum = 0;
        *r_bin = 0; *r_krem = target;
        for (int g = ngroups - 1; g >= 0; --g) {
            if (cum + gsum[g] >= target) {
                for (int b = g*32 + 31; b >= g*32; --b) {
                    if (cum + sh[b] >= target) { *r_bin = b; *r_krem = target - cum; return; }
                    cum += sh[b];
                }
            }
            cum += gsum[g];
        }
    }
}

// ---------------- seg_select: exact top-1000 within collected list + decode ------------
// phase 0: main path (requires KSEL <= m <= CAP, else set fb flag and defer)
// phase 1: fallback path (only fb segments; m <= KSEL allowed -> take all)
__global__ void seg_select_kernel(int phase,
                                  const float* __restrict__ r0, const float* __restrict__ r1,
                                  const float* __restrict__ r2, const float* __restrict__ l0,
                                  const float* __restrict__ l1, const float* __restrict__ l2)
{
    __shared__ unsigned sh[2048];
    __shared__ int s_bin; __shared__ unsigned s_krem;
    __shared__ unsigned s_T, s_allow, s_emit, s_tie;
    int seg = blockIdx.x;
    int n = seg / 3, lev = seg % 3;
    int tid = threadIdx.x;
    unsigned mraw = g_colcnt[seg];

    if (phase == 0) {
        if (mraw < KSEL || mraw > CAP) {
            if (tid == 0) g_fb[seg] = 1;
            return;
        }
    } else {
        if (!g_fb[seg]) return;
    }
    int m = (int)(mraw < CAP ? mraw : CAP);
    const unsigned* keys = g_colkey + (size_t)seg*CAP;
    const unsigned* poss = g_colpos + (size_t)seg*CAP;

    if (tid == 0) { s_emit = 0; s_tie = 0; }
    bool takeall = (m <= KSEL);

    if (takeall) {
        if (tid == 0) { s_T = 0; s_allow = 0; }
        __syncthreads();
    } else {
        for (int i = tid; i < 2048; i += blockDim.x) sh[i] = 0;
        __syncthreads();
        for (int i = tid; i < m; i += blockDim.x)
            atomicAdd(&sh[keys[i] >> 21], 1u);
        __syncthreads();
        bsel(sh, 2048, KSEL, &s_bin, &s_krem);
        __syncthreads();
        unsigned b1 = (unsigned)s_bin, want = s_krem;
        __syncthreads();
        for (int i = tid; i < 2048; i += blockDim.x) sh[i] = 0;
        __syncthreads();
        for (int i = tid; i < m; i += blockDim.x) {
            unsigned key = keys[i];
            if ((key >> 21) == b1) atomicAdd(&sh[(key >> 10) & 0x7FF], 1u);
        }
        __syncthreads();
        bsel(sh, 2048, want, &s_bin, &s_krem);
        __syncthreads();
        unsigned b2 = (unsigned)s_bin; want = s_krem;
        unsigned pfx2 = (b1 << 11) | b2;
        __syncthreads();
        for (int i = tid; i < 1024; i += blockDim.x) sh[i] = 0;
        __syncthreads();
        for (int i = tid; i < m; i += blockDim.x) {
            unsigned key = keys[i];
            if ((key >> 10) == pfx2) atomicAdd(&sh[key & 0x3FF], 1u);
        }
        __syncthreads();
        bsel(sh, 1024, want, &s_bin, &s_krem);
        __syncthreads();
        if (tid == 0) { s_T = (pfx2 << 10) | (unsigned)s_bin; s_allow = s_krem; }
        __syncthreads();
    }
    unsigned T = s_T, allow = s_allow;

    const float* rg; const float* lc; int HW; float sf;
    if (lev == 0)      { rg = r0 + (size_t)n*40000; lc = l0; HW = 10000; sf = 8.0f; }
    else if (lev == 1) { rg = r1 + (size_t)n*10000; lc = l1; HW = 2500;  sf = 16.0f; }
    else               { rg = r2 + (size_t)n*2500;  lc = l2; HW = 625;   sf = 32.0f; }

    for (int i = tid; i < m; i += blockDim.x) {
        unsigned key = keys[i];
        bool take;
        if (takeall) take = true;
        else {
            take = key > T;
            if (!take && key == T && allow) take = (atomicAdd(&s_tie, 1u) < allow);
        }
        if (!take) continue;
        unsigned slot = atomicAdd(&s_emit, 1u);
        unsigned pos = poss[i];
        int c = (int)pos / HW, hw = (int)pos - c * HW;
        float l = rg[hw]        * sf;
        float t = rg[HW + hw]   * sf;
        float r = rg[2*HW + hw] * sf;
        float b = rg[3*HW + hw] * sf;
        float x = lc[2*hw], y = lc[2*hw + 1];
        float x1 = fminf(fmaxf(x - l, 0.f), 800.f);
        float y1 = fminf(fmaxf(y - t, 0.f), 800.f);
        float x2 = fminf(fmaxf(x + r, 0.f), 800.f);
        float y2 = fminf(fmaxf(y + b, 0.f), 800.f);
        int g = n * NCAND + lev * KSEL + (int)slot;
        g_cbox[g] = make_float4(x1, y1, x2, y2);
        g_csc[g]  = sqrtf(__uint_as_float(key));
        g_ccls[g] = c + 1;
    }
}

// ---------------- fallback path (early-exits; exactness safety net) ----------------
__global__ __launch_bounds__(256) void fb_hist_kernel(
    const float* __restrict__ c0, const float* __restrict__ c1, const float* __restrict__ c2)
{
    int n = blockIdx.y, bx = blockIdx.x;
    int lev, b0, nb, vlo, vhi, ctro;
    const float* src;
    if (bx < 48)      { lev = 0; b0 = 0;  nb = 48; vlo = 0;      vhi = 200000; ctro = 0;
                        src = c0 + (size_t)n*800000; }
    else if (bx < 60) { lev = 1; b0 = 48; nb = 12; vlo = 200000; vhi = 250000; ctro = 10000;
                        src = c1 + (size_t)n*200000; }
    else              { lev = 2; b0 = 60; nb = 4;  vlo = 250000; vhi = 262500; ctro = 12500;
                        src = c2 + (size_t)n*50000; }
    int seg = n*3 + lev;
    if (!g_fb[seg]) return;

    __shared__ unsigned sh[2048];
    for (int i = threadIdx.x; i < 2048; i += blockDim.x) sh[i] = 0;
    __syncthreads();
    const float* tb = g_t + n*HWPAD + ctro;
    int HW = lev == 0 ? 10000 : (lev == 1 ? 2500 : 625);
    int vstride = nb * blockDim.x;
    int base = vlo * 4;
    for (int v = vlo + (bx - b0)*blockDim.x + threadIdx.x; v < vhi; v += vstride) {
        int e = v*4 - base;
        float4 xv = *reinterpret_cast<const float4*>(src + e);
        float xs[4] = {xv.x, xv.y, xv.z, xv.w};
        #pragma unroll
        for (int j = 0; j < 4; ++j) {
            int e2 = e + j; int c = e2 / HW; int hw = e2 - c*HW;
            float s = fsigm(xs[j]);
            if (s > 0.05f) {
                unsigned key = __float_as_uint(s * tb[hw]);
                if (key) atomicAdd(&sh[key >> 21], 1u);
            }
        }
    }
    __syncthreads();
    unsigned* gh = g_h2 + (size_t)seg * 2048;
    for (int i = threadIdx.x; i < 2048; i += blockDim.x)
        if (sh[i]) atomicAdd(&gh[i], sh[i]);
}

__global__ void fb_select_kernel()
{
    int seg = blockIdx.x;
    if (!g_fb[seg]) return;
    __shared__ unsigned csum[64];
    int tid = threadIdx.x;
    const unsigned* gh = g_h2 + (size_t)seg * 2048;
    if (tid < 64) {
        unsigned s = 0;
        for (int b = tid*32; b < tid*32 + 32; ++b) s += gh[b];
        csum[tid] = s;
    }
    __syncthreads();
    if (tid == 0) {
        unsigned cum = 0, F = 1;
        for (int ch = 63; ch >= 0; --ch) {
            if (cum + csum[ch] >= KSEL) {
                for (int b = ch*32 + 31; ; --b) {
                    cum += gh[b];
                    if (cum >= KSEL) { F = ((unsigned)b) << 21; if (F == 0) F = 1; break; }
                }
                break;
            }
            cum += csum[ch];
        }
        g_F[seg] = F;
        g_colcnt[seg] = 0;   // reset buffer for fb re-collect
    }
}

__global__ __launch_bounds__(256) void fb_collect_kernel(
    const float* __restrict__ c0, const float* __restrict__ c1, const float* __restrict__ c2)
{
    int n = blockIdx.y, bx = blockIdx.x;
    int lev, b0, nb, vlo, vhi, ctro;
    const float* src;
    if (bx < 48)      { lev = 0; b0 = 0;  nb = 48; vlo = 0;      vhi = 200000; ctro = 0;
                        src = c0 + (size_t)n*800000; }
    else if (bx < 60) { lev = 1; b0 = 48; nb = 12; vlo = 200000; vhi = 250000; ctro = 10000;
                        src = c1 + (size_t)n*200000; }
    else              { lev = 2; b0 = 60; nb = 4;  vlo = 250000; vhi = 262500; ctro = 12500;
                        src = c2 + (size_t)n*50000; }
    int seg = n*3 + lev;
    if (!g_fb[seg]) return;
    unsigned F = g_F[seg];
    const float* tb = g_t + n*HWPAD + ctro;
    int HW = lev == 0 ? 10000 : (lev == 1 ? 2500 : 625);
    int vstride = nb * blockDim.x;
    int base = vlo * 4;
    for (int v = vlo + (bx - b0)*blockDim.x + threadIdx.x; v < vhi; v += vstride) {
        int e = v*4 - base;
        float4 xv = *reinterpret_cast<const float4*>(src + e);
        float xs[4] = {xv.x, xv.y, xv.z, xv.w};
        #pragma unroll
        for (int j = 0; j < 4; ++j) {
            int e2 = e + j; int c = e2 / HW; int hw = e2 - c*HW;
            float s = fsigm(xs[j]);
            unsigned key = (s > 0.05f) ? __float_as_uint(s * tb[hw]) : 0u;
            if (key >= F && key) {
                unsigned idx = atomicAdd(&g_colcnt[seg], 1u);
                if (idx < CAP) {
                    g_colkey[(size_t)seg*CAP + idx] = key;
                    g_colpos[(size_t)seg*CAP + idx] = (unsigned)(e + j);
                }
            }
        }
    }
}

// ---------------- greedy NMS: all loop state in smem/registers ----------------
#define NTH 512
#define KC  6    // 512*6 = 3072 >= NCAND
__global__ __launch_bounds__(NTH) void nms_kernel(float* __restrict__ out)
{
    extern __shared__ unsigned char smraw[];
    float* ox1 = (float*)smraw;          // offset coords (for IoU)
    float* oy1 = ox1 + NCAND;
    float* ox2 = oy1 + NCAND;
    float* oy2 = ox2 + NCAND;
    float* oar = oy2 + NCAND;
    float* ex1 = oar + NCAND;            // exact output coords
    float* ey1 = ex1 + NCAND;
    float* ex2 = ey1 + NCAND;
    float* ey2 = ex2 + NCAND;
    int*   scl = (int*)(ey2 + NCAND);

    __shared__ float rs[NTH/32]; __shared__ int ri[NTH/32];
    __shared__ float sB; __shared__ int sI;

    int n = blockIdx.x;
    int tid = threadIdx.x;
    int lane = tid & 31, wid = tid >> 5;

    float sc[KC], bx1[KC], by1[KC], bx2[KC], by2[KC], ba[KC];
    #pragma unroll
    for (int k = 0; k < KC; ++k) {
        int i = tid + k * NTH;
        float s = -2.0f, x1 = 0.f, y1 = 0.f, x2 = 0.f, y2 = 0.f, a = 0.f;
        if (i < NCAND) {
            s = g_csc[n*NCAND + i];
            float4 b = g_cbox[n*NCAND + i];
            int c = g_ccls[n*NCAND + i];
            if (s > 0.f) {
                float off = (float)c * 4096.0f;
                x1 = b.x + off; y1 = b.y + off; x2 = b.z + off; y2 = b.w + off;
                a = (x2 - x1) * (y2 - y1);
            } else s = -1.0f;
            ox1[i] = x1; oy1[i] = y1; ox2[i] = x2; oy2[i] = y2; oar[i] = a;
            ex1[i] = b.x; ey1[i] = b.y; ex2[i] = b.z; ey2[i] = b.w;
            scl[i] = c;
        }
        sc[k] = s; bx1[k] = x1; by1[k] = y1; bx2[k] = x2; by2[k] = y2; ba[k] = a;
    }
    __syncthreads();

    for (int it = 0; it < NPICK; ++it) {
        float bs = -3.0f; int bi = 0x7FFFFFFF;
        #pragma unroll
        for (int k = 0; k < KC; ++k)
            if (sc[k] > bs) { bs = sc[k]; bi = tid + k*NTH; }
        #pragma unroll
        for (int o = 16; o; o >>= 1) {
            float s2 = __shfl_down_sync(0xFFFFFFFFu, bs, o);
            int   i2 = __shfl_down_sync(0xFFFFFFFFu, bi, o);
            if (s2 > bs || (s2 == bs && i2 < bi)) { bs = s2; bi = i2; }
        }
        if (lane == 0) { rs[wid] = bs; ri[wid] = bi; }
        __syncthreads();
        if (wid == 0) {
            float s = (lane < NTH/32) ? rs[lane] : -3.0f;
            int   b = (lane < NTH/32) ? ri[lane] : 0x7FFFFFFF;
            #pragma unroll
            for (int o = 8; o; o >>= 1) {
                float s2 = __shfl_down_sync(0xFFFFFFFFu, s, o);
                int   b2 = __shfl_down_sync(0xFFFFFFFFu, b, o);
                if (s2 > s || (s2 == s && b2 < b)) { s = s2; b = b2; }
            }
            if (lane == 0) { sB = s; sI = b; }
        }
        __syncthreads();
        float pbs = sB; int pbi = sI;
        bool keep = pbs > 0.0f;

        if (tid < 7) {
            int row = n * NPICK + it;
            float val = 0.f;
            if (keep) {
                if (tid == 0) val = ex1[pbi];
                else if (tid == 1) val = ey1[pbi];
                else if (tid == 2) val = ex2[pbi];
                else if (tid == 3) val = ey2[pbi];
                else if (tid == 4) val = pbs;
                else if (tid == 5) val = (float)scl[pbi];
                else               val = 1.0f;
            }
            if (tid < 4)       out[OFS_BOX + (n*NPICK + it)*4 + tid] = val;
            else if (tid == 4) out[OFS_SC + row] = val;
            else if (tid == 5) out[OFS_CL + row] = val;
            else               out[OFS_KP + row] = val;
        }

        float px1 = ox1[pbi], py1 = oy1[pbi], px2 = ox2[pbi], py2 = oy2[pbi], pa = oar[pbi];
        #pragma unroll
        for (int k = 0; k < KC; ++k) {
            if (tid + k*NTH == pbi) { sc[k] = -1.0f; continue; }
            float xx1 = fmaxf(px1, bx1[k]);
            float yy1 = fmaxf(py1, by1[k]);
            float xx2 = fminf(px2, bx2[k]);
            float yy2 = fminf(py2, by2[k]);
            float inter = fmaxf(xx2 - xx1, 0.f) * fmaxf(yy2 - yy1, 0.f);
            float iou = inter / (ba[k] + pa - inter + 1e-9f);
            if (iou > 0.6f && sc[k] > -1.5f) sc[k] = -1.0f;
        }
    }
}

// ---------------- launch ----------------
extern "C" void kernel_launch(void* const* d_in, const int* in_sizes, int n_in,
                              void* d_out, int out_size)
{
    const float *loc0, *loc1, *loc2, *cls0, *cls1, *cls2;
    const float *reg0, *reg1, *reg2, *ctr0, *ctr1, *ctr2;
    if (in_sizes[1] == 16 * 80 * 10000) {
        loc0 = (const float*)d_in[0];  cls0 = (const float*)d_in[1];
        reg0 = (const float*)d_in[2];  ctr0 = (const float*)d_in[3];
        loc1 = (const float*)d_in[4];  cls1 = (const float*)d_in[5];
        reg1 = (const float*)d_in[6];  ctr1 = (const float*)d_in[7];
        loc2 = (const float*)d_in[8];  cls2 = (const float*)d_in[9];
        reg2 = (const float*)d_in[10]; ctr2 = (const float*)d_in[11];
    } else {
        loc0 = (const float*)d_in[0];  loc1 = (const float*)d_in[1];  loc2 = (const float*)d_in[2];
        cls0 = (const float*)d_in[3];  cls1 = (const float*)d_in[4];  cls2 = (const float*)d_in[5];
        reg0 = (const float*)d_in[6];  reg1 = (const float*)d_in[7];  reg2 = (const float*)d_in[8];
        ctr0 = (const float*)d_in[9];  ctr1 = (const float*)d_in[10]; ctr2 = (const float*)d_in[11];
    }
    float* out = (float*)d_out;

    const int NMS_SMEM = 10 * NCAND * 4;
    cudaFuncSetAttribute(nms_kernel, cudaFuncAttributeMaxDynamicSharedMemorySize, NMS_SMEM);

    init_kernel<<<416, 256>>>(ctr0, ctr1, ctr2);
    scan_kernel<<<dim3(64, NIMG), 256>>>(cls0, cls1, cls2);
    seg_select_kernel<<<NIMG*3, 256>>>(0, reg0, reg1, reg2, loc0, loc1, loc2);
    fb_hist_kernel<<<dim3(64, NIMG), 256>>>(cls0, cls1, cls2);
    fb_select_kernel<<<NIMG*3, 256>>>();
    fb_collect_kernel<<<dim3(64, NIMG), 256>>>(cls0, cls1, cls2);
    seg_select_kernel<<<NIMG*3, 256>>>(1, reg0, reg1, reg2, loc0, loc1, loc2);
    nms_kernel<<<NIMG, NTH, NMS_SMEM>>>(out);
}

// round 13
// speedup vs baseline: 1.0057x; 1.0057x over previous
#include <cuda_runtime.h>
#include <math.h>
#include <float.h>

#define NIMG   16
#define KSEL   1000
#define NCAND  3000
#define NPICK  100
#define HWTOT  13125
#define HWPAD  13128
#define MTOT   1050000
#define CAP    262144

// Output layout (float32, concatenated tuple: boxes, scores, classes, keep)
#define OFS_BOX 0
#define OFS_SC  (NIMG*NPICK*4)
#define OFS_CL  (OFS_SC + NIMG*NPICK)
#define OFS_KP  (OFS_CL + NIMG*NPICK)

// ---------------- scratch (device globals, no allocation) ----------------
__device__ float    g_t[NIMG*HWPAD];      // sigmoid(ctr) per location
__device__ float    g_xc0[NIMG*HWPAD];    // static cutoff: x >= xc0 => key may be >= 0.5
__device__ unsigned g_h2[NIMG*3*2048];    // fallback coarse hist
__device__ unsigned g_F[NIMG*3];
__device__ unsigned g_fb[NIMG*3];
__device__ unsigned g_colcnt[NIMG*3];
__device__ unsigned g_colkey[(size_t)NIMG*3*CAP];
__device__ unsigned g_colpos[(size_t)NIMG*3*CAP];
__device__ float4   g_cbox[NIMG*NCAND];
__device__ float    g_csc[NIMG*NCAND];
__device__ int      g_ccls[NIMG*NCAND];

__device__ __forceinline__ float fsigm(float x) { return __fdividef(1.0f, 1.0f + __expf(-x)); }

// Conservative x-cutoff: any element whose exact key (= fl(fsigm(x)*t)) can be
// >= Fv satisfies x >= cutval(Fv,t).
__device__ __forceinline__ float cutval(float Fv, float t)
{
    if (!(t > Fv)) return (t == Fv) ? 16.0f : FLT_MAX;
    float r = Fv / (t - Fv);
    if (r > 1.0e6f) return -1000.0f;
    return logf(r) - (0.05f + 5e-6f * r);
}

// ---------------- init: tables + zero scratch ----------------
__global__ void init_kernel(const float* __restrict__ c0, const float* __restrict__ c1,
                            const float* __restrict__ c2)
{
    int i0 = blockIdx.x * blockDim.x + threadIdx.x;
    int st = gridDim.x * blockDim.x;
    for (int j = i0; j < NIMG*3*2048; j += st) g_h2[j] = 0;
    for (int j = i0; j < NIMG*3; j += st) { g_colcnt[j] = 0; g_fb[j] = 0; }
    for (int j = i0; j < NIMG*NCAND; j += st) {
        g_csc[j] = -1.0f; g_ccls[j] = 0;
        g_cbox[j] = make_float4(0.f, 0.f, 0.f, 0.f);
    }
    for (int j = i0; j < NIMG*HWPAD; j += st) {
        int n = j / HWPAD, r = j - n * HWPAD;
        float t = 0.0f;
        if (r < 10000)      t = fsigm(c0[n*10000 + r]);
        else if (r < 12500) t = fsigm(c1[n*2500  + (r - 10000)]);
        else if (r < HWTOT) t = fsigm(c2[n*625   + (r - 12500)]);
        g_t[j]   = t;
        g_xc0[j] = cutval(0.5f, t);
    }
}

// ---------------- the single big scan: filter + exact append of keys >= 0.5 ----------
template<int HW, bool VEC>
__device__ __forceinline__ void scan_body(int e, float4 xv, const float* __restrict__ tb,
                                          const float* __restrict__ cb, int seg, unsigned lane)
{
    float xs[4] = {xv.x, xv.y, xv.z, xv.w};
    float cs[4];
    int hwb = 0;
    if (VEC) {
        int c = e / HW; hwb = e - c*HW;
        float4 cv = *reinterpret_cast<const float4*>(cb + hwb);
        cs[0] = cv.x; cs[1] = cv.y; cs[2] = cv.z; cs[3] = cv.w;
    }
    #pragma unroll
    for (int j = 0; j < 4; ++j) {
        bool take = false; unsigned key = 0;
        int hw;
        if (VEC) hw = hwb + j;
        else { int e2 = e + j; int c = e2 / HW; hw = e2 - c*HW; }
        float cut = VEC ? cs[j] : cb[hw];
        if (xs[j] >= cut) {
            float s = fsigm(xs[j]);
            key = __float_as_uint(s * tb[hw]);
            take = key >= 0x3F000000u;     // exact: score >= 0.5
        }
        unsigned mask = __activemask();
        unsigned bal = __ballot_sync(mask, take);
        if (take) {
            int leader = __ffs(bal) - 1;
            unsigned rank = __popc(bal & ((1u << lane) - 1u));
            unsigned basep = 0;
            if ((int)lane == leader)
                basep = atomicAdd(&g_colcnt[seg], (unsigned)__popc(bal));
            basep = __shfl_sync(bal, basep, leader);
            unsigned idx = basep + rank;
            if (idx < CAP) {
                g_colkey[(size_t)seg*CAP + idx] = key;
                g_colpos[(size_t)seg*CAP + idx] = (unsigned)(e + j);
            }
        }
    }
}

__global__ __launch_bounds__(256) void scan_kernel(
    const float* __restrict__ c0, const float* __restrict__ c1, const float* __restrict__ c2)
{
    int n = blockIdx.y, bx = blockIdx.x;
    int lev, b0, nb, vlo, vhi, ctro;
    const float* src;
    if (bx < 48)      { lev = 0; b0 = 0;  nb = 48; vlo = 0;      vhi = 200000; ctro = 0;
                        src = c0 + (size_t)n*800000; }
    else if (bx < 60) { lev = 1; b0 = 48; nb = 12; vlo = 200000; vhi = 250000; ctro = 10000;
                        src = c1 + (size_t)n*200000; }
    else              { lev = 2; b0 = 60; nb = 4;  vlo = 250000; vhi = 262500; ctro = 12500;
                        src = c2 + (size_t)n*50000; }
    int seg = n*3 + lev;
    const float* tb = g_t   + n*HWPAD + ctro;
    const float* cb = g_xc0 + n*HWPAD + ctro;
    int vstride = nb * blockDim.x;
    int base = vlo * 4;
    unsigned lane = threadIdx.x & 31;

    for (int v = vlo + (bx - b0)*blockDim.x + threadIdx.x; v < vhi; v += vstride) {
        int e = v*4 - base;
        float4 xv = *reinterpret_cast<const float4*>(src + e);
        if (lev == 0)      scan_body<10000, true>(e, xv, tb, cb, seg, lane);
        else if (lev == 1) scan_body<2500, true>(e, xv, tb, cb, seg, lane);
        else               scan_body<625, false>(e, xv, tb, cb, seg, lane);
    }
}

// ---------------- block-level histogram select (descending) ----------------
__device__ __forceinline__ void bsel(unsigned* sh, int nb, unsigned target,
                                     int* r_bin, unsigned* r_krem)
{
    __shared__ unsigned gsum[64];
    int tid = threadIdx.x;
    int ngroups = nb / 32;
    if (tid < ngroups) {
        unsigned s = 0;
        for (int j = 0; j < 32; ++j) s += sh[tid*32 + j];
        gsum[tid] = s;
    }
    __syncthreads();
    if (tid == 0) {
        unsigned cum = 0;
        *r_bin = 0; *r_krem = target;
        for (int g = ngroups - 1; g >= 0; --g) {
            if (cum + gsum[g] >= target) {
                for (int b = g*32 + 31; b >= g*32; --b) {
                    if (cum + sh[b] >= target) { *r_bin = b; *r_krem = target - cum; return; }
                    cum += sh[b];
                }
            }
            cum += gsum[g];
        }
    }
}

// ---------------- seg_select: exact top-1000 within collected list + decode ------------
// phase 0: main path (requires KSEL <= m <= CAP, else set fb flag and defer)
// phase 1: fallback path (only fb segments; m <= KSEL allowed -> take all)
__global__ void seg_select_kernel(int phase,
                                  const float* __restrict__ r0, const float* __restrict__ r1,
                                  const float* __restrict__ r2, const float* __restrict__ l0,
                                  const float* __restrict__ l1, const float* __restrict__ l2)
{
    __shared__ unsigned sh[2048];
    __shared__ int s_bin; __shared__ unsigned s_krem;
    __shared__ unsigned s_T, s_allow, s_emit, s_tie;
    int seg = blockIdx.x;
    int n = seg / 3, lev = seg % 3;
    int tid = threadIdx.x;
    unsigned mraw = g_colcnt[seg];

    if (phase == 0) {
        if (mraw < KSEL || mraw > CAP) {
            if (tid == 0) g_fb[seg] = 1;
            return;
        }
    } else {
        if (!g_fb[seg]) return;
    }
    int m = (int)(mraw < CAP ? mraw : CAP);
    const unsigned* keys = g_colkey + (size_t)seg*CAP;
    const unsigned* poss = g_colpos + (size_t)seg*CAP;

    if (tid == 0) { s_emit = 0; s_tie = 0; }
    bool takeall = (m <= KSEL);

    if (takeall) {
        if (tid == 0) { s_T = 0; s_allow = 0; }
        __syncthreads();
    } else {
        for (int i = tid; i < 2048; i += blockDim.x) sh[i] = 0;
        __syncthreads();
        for (int i = tid; i < m; i += blockDim.x)
            atomicAdd(&sh[keys[i] >> 21], 1u);
        __syncthreads();
        bsel(sh, 2048, KSEL, &s_bin, &s_krem);
        __syncthreads();
        unsigned b1 = (unsigned)s_bin, want = s_krem;
        __syncthreads();
        for (int i = tid; i < 2048; i += blockDim.x) sh[i] = 0;
        __syncthreads();
        for (int i = tid; i < m; i += blockDim.x) {
            unsigned key = keys[i];
            if ((key >> 21) == b1) atomicAdd(&sh[(key >> 10) & 0x7FF], 1u);
        }
        __syncthreads();
        bsel(sh, 2048, want, &s_bin, &s_krem);
        __syncthreads();
        unsigned b2 = (unsigned)s_bin; want = s_krem;
        unsigned pfx2 = (b1 << 11) | b2;
        __syncthreads();
        for (int i = tid; i < 1024; i += blockDim.x) sh[i] = 0;
        __syncthreads();
        for (int i = tid; i < m; i += blockDim.x) {
            unsigned key = keys[i];
            if ((key >> 10) == pfx2) atomicAdd(&sh[key & 0x3FF], 1u);
        }
        __syncthreads();
        bsel(sh, 1024, want, &s_bin, &s_krem);
        __syncthreads();
        if (tid == 0) { s_T = (pfx2 << 10) | (unsigned)s_bin; s_allow = s_krem; }
        __syncthreads();
    }
    unsigned T = s_T, allow = s_allow;

    const float* rg; const float* lc; int HW; float sf;
    if (lev == 0)      { rg = r0 + (size_t)n*40000; lc = l0; HW = 10000; sf = 8.0f; }
    else if (lev == 1) { rg = r1 + (size_t)n*10000; lc = l1; HW = 2500;  sf = 16.0f; }
    else               { rg = r2 + (size_t)n*2500;  lc = l2; HW = 625;   sf = 32.0f; }

    for (int i = tid; i < m; i += blockDim.x) {
        unsigned key = keys[i];
        bool take;
        if (takeall) take = true;
        else {
            take = key > T;
            if (!take && key == T && allow) take = (atomicAdd(&s_tie, 1u) < allow);
        }
        if (!take) continue;
        unsigned slot = atomicAdd(&s_emit, 1u);
        unsigned pos = poss[i];
        int c = (int)pos / HW, hw = (int)pos - c * HW;
        float l = rg[hw]        * sf;
        float t = rg[HW + hw]   * sf;
        float r = rg[2*HW + hw] * sf;
        float b = rg[3*HW + hw] * sf;
        float x = lc[2*hw], y = lc[2*hw + 1];
        float x1 = fminf(fmaxf(x - l, 0.f), 800.f);
        float y1 = fminf(fmaxf(y - t, 0.f), 800.f);
        float x2 = fminf(fmaxf(x + r, 0.f), 800.f);
        float y2 = fminf(fmaxf(y + b, 0.f), 800.f);
        int g = n * NCAND + lev * KSEL + (int)slot;
        g_cbox[g] = make_float4(x1, y1, x2, y2);
        g_csc[g]  = sqrtf(__uint_as_float(key));
        g_ccls[g] = c + 1;
    }
}

// ---------------- fallback path (early-exits; exactness safety net) ----------------
__global__ __launch_bounds__(256) void fb_hist_kernel(
    const float* __restrict__ c0, const float* __restrict__ c1, const float* __restrict__ c2)
{
    int n = blockIdx.y, bx = blockIdx.x;
    int lev, b0, nb, vlo, vhi, ctro;
    const float* src;
    if (bx < 48)      { lev = 0; b0 = 0;  nb = 48; vlo = 0;      vhi = 200000; ctro = 0;
                        src = c0 + (size_t)n*800000; }
    else if (bx < 60) { lev = 1; b0 = 48; nb = 12; vlo = 200000; vhi = 250000; ctro = 10000;
                        src = c1 + (size_t)n*200000; }
    else              { lev = 2; b0 = 60; nb = 4;  vlo = 250000; vhi = 262500; ctro = 12500;
                        src = c2 + (size_t)n*50000; }
    int seg = n*3 + lev;
    if (!g_fb[seg]) return;

    __shared__ unsigned sh[2048];
    for (int i = threadIdx.x; i < 2048; i += blockDim.x) sh[i] = 0;
    __syncthreads();
    const float* tb = g_t + n*HWPAD + ctro;
    int HW = lev == 0 ? 10000 : (lev == 1 ? 2500 : 625);
    int vstride = nb * blockDim.x;
    int base = vlo * 4;
    for (int v = vlo + (bx - b0)*blockDim.x + threadIdx.x; v < vhi; v += vstride) {
        int e = v*4 - base;
        float4 xv = *reinterpret_cast<const float4*>(src + e);
        float xs[4] = {xv.x, xv.y, xv.z, xv.w};
        #pragma unroll
        for (int j = 0; j < 4; ++j) {
            int e2 = e + j; int c = e2 / HW; int hw = e2 - c*HW;
            float s = fsigm(xs[j]);
            if (s > 0.05f) {
                unsigned key = __float_as_uint(s * tb[hw]);
                if (key) atomicAdd(&sh[key >> 21], 1u);
            }
        }
    }
    __syncthreads();
    unsigned* gh = g_h2 + (size_t)seg * 2048;
    for (int i = threadIdx.x; i < 2048; i += blockDim.x)
        if (sh[i]) atomicAdd(&gh[i], sh[i]);
}

__global__ void fb_select_kernel()
{
    int seg = blockIdx.x;
    if (!g_fb[seg]) return;
    __shared__ unsigned csum[64];
    int tid = threadIdx.x;
    const unsigned* gh = g_h2 + (size_t)seg * 2048;
    if (tid < 64) {
        unsigned s = 0;
        for (int b = tid*32; b < tid*32 + 32; ++b) s += gh[b];
        csum[tid] = s;
    }
    __syncthreads();
    if (tid == 0) {
        unsigned cum = 0, F = 1;
        for (int ch = 63; ch >= 0; --ch) {
            if (cum + csum[ch] >= KSEL) {
                for (int b = ch*32 + 31; ; --b) {
                    cum += gh[b];
                    if (cum >= KSEL) { F = ((unsigned)b) << 21; if (F == 0) F = 1; break; }
                }
                break;
            }
            cum += csum[ch];
        }
        g_F[seg] = F;
        g_colcnt[seg] = 0;   // reset buffer for fb re-collect
    }
}

__global__ __launch_bounds__(256) void fb_collect_kernel(
    const float* __restrict__ c0, const float* __restrict__ c1, const float* __restrict__ c2)
{
    int n = blockIdx.y, bx = blockIdx.x;
    int lev, b0, nb, vlo, vhi, ctro;
    const float* src;
    if (bx < 48)      { lev = 0; b0 = 0;  nb = 48; vlo = 0;      vhi = 200000; ctro = 0;
                        src = c0 + (size_t)n*800000; }
    else if (bx < 60) { lev = 1; b0 = 48; nb = 12; vlo = 200000; vhi = 250000; ctro = 10000;
                        src = c1 + (size_t)n*200000; }
    else              { lev = 2; b0 = 60; nb = 4;  vlo = 250000; vhi = 262500; ctro = 12500;
                        src = c2 + (size_t)n*50000; }
    int seg = n*3 + lev;
    if (!g_fb[seg]) return;
    unsigned F = g_F[seg];
    const float* tb = g_t + n*HWPAD + ctro;
    int HW = lev == 0 ? 10000 : (lev == 1 ? 2500 : 625);
    int vstride = nb * blockDim.x;
    int base = vlo * 4;
    for (int v = vlo + (bx - b0)*blockDim.x + threadIdx.x; v < vhi; v += vstride) {
        int e = v*4 - base;
        float4 xv = *reinterpret_cast<const float4*>(src + e);
        float xs[4] = {xv.x, xv.y, xv.z, xv.w};
        #pragma unroll
        for (int j = 0; j < 4; ++j) {
            int e2 = e + j; int c = e2 / HW; int hw = e2 - c*HW;
            float s = fsigm(xs[j]);
            unsigned key = (s > 0.05f) ? __float_as_uint(s * tb[hw]) : 0u;
            if (key >= F && key) {
                unsigned idx = atomicAdd(&g_colcnt[seg], 1u);
                if (idx < CAP) {
                    g_colkey[(size_t)seg*CAP + idx] = key;
                    g_colpos[(size_t)seg*CAP + idx] = (unsigned)(e + j);
                }
            }
        }
    }
}

// ---------------- greedy NMS: all loop state in smem/registers ----------------
#define NTH 512
#define KC  6    // 512*6 = 3072 >= NCAND
__global__ __launch_bounds__(NTH) void nms_kernel(float* __restrict__ out)
{
    extern __shared__ unsigned char smraw[];
    float* ox1 = (float*)smraw;          // offset coords (for IoU)
    float* oy1 = ox1 + NCAND;
    float* ox2 = oy1 + NCAND;
    float* oy2 = ox2 + NCAND;
    float* oar = oy2 + NCAND;
    float* ex1 = oar + NCAND;            // exact output coords
    float* ey1 = ex1 + NCAND;
    float* ex2 = ey1 + NCAND;
    float* ey2 = ex2 + NCAND;
    int*   scl = (int*)(ey2 + NCAND);

    __shared__ float rs[NTH/32]; __shared__ int ri[NTH/32];
    __shared__ float sB; __shared__ int sI;

    int n = blockIdx.x;
    int tid = threadIdx.x;
    int lane = tid & 31, wid = tid >> 5;

    float sc[KC], bx1[KC], by1[KC], bx2[KC], by2[KC], ba[KC];
    #pragma unroll
    for (int k = 0; k < KC; ++k) {
        int i = tid + k * NTH;
        float s = -2.0f, x1 = 0.f, y1 = 0.f, x2 = 0.f, y2 = 0.f, a = 0.f;
        if (i < NCAND) {
            s = g_csc[n*NCAND + i];
            float4 b = g_cbox[n*NCAND + i];
            int c = g_ccls[n*NCAND + i];
            if (s > 0.f) {
                float off = (float)c * 4096.0f;
                x1 = b.x + off; y1 = b.y + off; x2 = b.z + off; y2 = b.w + off;
                a = (x2 - x1) * (y2 - y1);
            } else s = -1.0f;
            ox1[i] = x1; oy1[i] = y1; ox2[i] = x2; oy2[i] = y2; oar[i] = a;
            ex1[i] = b.x; ey1[i] = b.y; ex2[i] = b.z; ey2[i] = b.w;
            scl[i] = c;
        }
        sc[k] = s; bx1[k] = x1; by1[k] = y1; bx2[k] = x2; by2[k] = y2; ba[k] = a;
    }
    __syncthreads();

    for (int it = 0; it < NPICK; ++it) {
        float bs = -3.0f; int bi = 0x7FFFFFFF;
        #pragma unroll
        for (int k = 0; k < KC; ++k)
            if (sc[k] > bs) { bs = sc[k]; bi = tid + k*NTH; }
        #pragma unroll
        for (int o = 16; o; o >>= 1) {
            float s2 = __shfl_down_sync(0xFFFFFFFFu, bs, o);
            int   i2 = __shfl_down_sync(0xFFFFFFFFu, bi, o);
            if (s2 > bs || (s2 == bs && i2 < bi)) { bs = s2; bi = i2; }
        }
        if (lane == 0) { rs[wid] = bs; ri[wid] = bi; }
        __syncthreads();
        if (wid == 0) {
            float s = (lane < NTH/32) ? rs[lane] : -3.0f;
            int   b = (lane < NTH/32) ? ri[lane] : 0x7FFFFFFF;
            #pragma unroll
            for (int o = 8; o; o >>= 1) {
                float s2 = __shfl_down_sync(0xFFFFFFFFu, s, o);
                int   b2 = __shfl_down_sync(0xFFFFFFFFu, b, o);
                if (s2 > s || (s2 == s && b2 < b)) { s = s2; b = b2; }
            }
            if (lane == 0) { sB = s; sI = b; }
        }
        __syncthreads();
        float pbs = sB; int pbi = sI;
        bool keep = pbs > 0.0f;

        if (tid < 7) {
            int row = n * NPICK + it;
            float val = 0.f;
            if (keep) {
                if (tid == 0) val = ex1[pbi];
                else if (tid == 1) val = ey1[pbi];
                else if (tid == 2) val = ex2[pbi];
                else if (tid == 3) val = ey2[pbi];
                else if (tid == 4) val = pbs;
                else if (tid == 5) val = (float)scl[pbi];
                else               val = 1.0f;
            }
            if (tid < 4)       out[OFS_BOX + (n*NPICK + it)*4 + tid] = val;
            else if (tid == 4) out[OFS_SC + row] = val;
            else if (tid == 5) out[OFS_CL + row] = val;
            else               out[OFS_KP + row] = val;
        }

        float px1 = ox1[pbi], py1 = oy1[pbi], px2 = ox2[pbi], py2 = oy2[pbi], pa = oar[pbi];
        #pragma unroll
        for (int k = 0; k < KC; ++k) {
            if (tid + k*NTH == pbi) { sc[k] = -1.0f; continue; }
            float xx1 = fmaxf(px1, bx1[k]);
            float yy1 = fmaxf(py1, by1[k]);
            float xx2 = fminf(px2, bx2[k]);
            float yy2 = fminf(py2, by2[k]);
            float inter = fmaxf(xx2 - xx1, 0.f) * fmaxf(yy2 - yy1, 0.f);
            float iou = inter / (ba[k] + pa - inter + 1e-9f);
            if (iou > 0.6f && sc[k] > -1.5f) sc[k] = -1.0f;
        }
    }
}

// ---------------- launch ----------------
extern "C" void kernel_launch(void* const* d_in, const int* in_sizes, int n_in,
                              void* d_out, int out_size)
{
    const float *loc0, *loc1, *loc2, *cls0, *cls1, *cls2;
    const float *reg0, *reg1, *reg2, *ctr0, *ctr1, *ctr2;
    if (in_sizes[1] == 16 * 80 * 10000) {
        loc0 = (const float*)d_in[0];  cls0 = (const float*)d_in[1];
        reg0 = (const float*)d_in[2];  ctr0 = (const float*)d_in[3];
        loc1 = (const float*)d_in[4];  cls1 = (const float*)d_in[5];
        reg1 = (const float*)d_in[6];  ctr1 = (const float*)d_in[7];
        loc2 = (const float*)d_in[8];  cls2 = (const float*)d_in[9];
        reg2 = (const float*)d_in[10]; ctr2 = (const float*)d_in[11];
    } else {
        loc0 = (const float*)d_in[0];  loc1 = (const float*)d_in[1];  loc2 = (const float*)d_in[2];
        cls0 = (const float*)d_in[3];  cls1 = (const float*)d_in[4];  cls2 = (const float*)d_in[5];
        reg0 = (const float*)d_in[6];  reg1 = (const float*)d_in[7];  reg2 = (const float*)d_in[8];
        ctr0 = (const float*)d_in[9];  ctr1 = (const float*)d_in[10]; ctr2 = (const float*)d_in[11];
    }
    float* out = (float*)d_out;

    const int NMS_SMEM = 10 * NCAND * 4;
    cudaFuncSetAttribute(nms_kernel, cudaFuncAttributeMaxDynamicSharedMemorySize, NMS_SMEM);

    init_kernel<<<416, 256>>>(ctr0, ctr1, ctr2);
    scan_kernel<<<dim3(64, NIMG), 256>>>(cls0, cls1, cls2);
    seg_select_kernel<<<NIMG*3, 256>>>(0, reg0, reg1, reg2, loc0, loc1, loc2);
    fb_hist_kernel<<<dim3(64, NIMG), 256>>>(cls0, cls1, cls2);
    fb_select_kernel<<<NIMG*3, 256>>>();
    fb_collect_kernel<<<dim3(64, NIMG), 256>>>(cls0, cls1, cls2);
    seg_select_kernel<<<NIMG*3, 256>>>(1, reg0, reg1, reg2, loc0, loc1, loc2);
    nms_kernel<<<NIMG, NTH, NMS_SMEM>>>(out);
}

// round 14
// speedup vs baseline: 1.3522x; 1.3445x over previous
#include <cuda_runtime.h>
#include <math.h>
#include <float.h>

#define NIMG   16
#define KSEL   1000
#define NCAND  3000
#define NPICK  100
#define HWTOT  13125
#define HWPAD  13128
#define MTOT   1050000
#define CAP    131072
#define NB1    4096

// Output layout (float32, concatenated tuple: boxes, scores, classes, keep)
#define OFS_BOX 0
#define OFS_SC  (NIMG*NPICK*4)
#define OFS_CL  (OFS_SC + NIMG*NPICK)
#define OFS_KP  (OFS_CL + NIMG*NPICK)

// ---------------- scratch (device globals, no allocation) ----------------
__device__ float    g_t[NIMG*HWPAD];      // sigmoid(ctr) per location
__device__ float    g_xc0[NIMG*HWPAD];    // static cutoff: x >= xc0 => key may be >= 0.5
__device__ float    g_xcF[NIMG*HWPAD];    // per-segment cutoff for F
__device__ unsigned g_h1[NIMG*3*NB1];     // fine hist over [0.5,1)
__device__ unsigned g_h2[NIMG*3*2048];    // fallback coarse hist
__device__ unsigned g_F[NIMG*3];
__device__ unsigned g_fb[NIMG*3];
__device__ unsigned g_colcnt[NIMG*3];
__device__ unsigned g_colkey[(size_t)NIMG*3*CAP];
__device__ unsigned g_colpos[(size_t)NIMG*3*CAP];
__device__ float4   g_cbox[NIMG*NCAND];
__device__ float    g_csc[NIMG*NCAND];
__device__ int      g_ccls[NIMG*NCAND];

__device__ __forceinline__ float fsigm(float x) { return __fdividef(1.0f, 1.0f + __expf(-x)); }

// Conservative x-cutoff: every element whose exact key (= fl(fsigm(x)*t)) can be
// >= Fv satisfies x >= cutval(Fv,t).
__device__ __forceinline__ float cutval(float Fv, float t)
{
    if (!(t > Fv)) return (t == Fv) ? 16.0f : FLT_MAX;
    float r = Fv / (t - Fv);
    if (r > 1.0e6f) return -1000.0f;
    return logf(r) - (0.05f + 5e-6f * r);
}

// ---------------- init: tables + zero scratch ----------------
__global__ void init_kernel(const float* __restrict__ c0, const float* __restrict__ c1,
                            const float* __restrict__ c2)
{
    int i0 = blockIdx.x * blockDim.x + threadIdx.x;
    int st = gridDim.x * blockDim.x;
    for (int j = i0; j < NIMG*3*NB1; j += st) g_h1[j] = 0;
    for (int j = i0; j < NIMG*3*2048; j += st) g_h2[j] = 0;
    for (int j = i0; j < NIMG*3; j += st) g_colcnt[j] = 0;
    for (int j = i0; j < NIMG*NCAND; j += st) {
        g_csc[j] = -1.0f; g_ccls[j] = 0;
        g_cbox[j] = make_float4(0.f, 0.f, 0.f, 0.f);
    }
    for (int j = i0; j < NIMG*HWPAD; j += st) {
        int n = j / HWPAD, r = j - n * HWPAD;
        float t = 0.0f;
        if (r < 10000)      t = fsigm(c0[n*10000 + r]);
        else if (r < 12500) t = fsigm(c1[n*2500  + (r - 10000)]);
        else if (r < HWTOT) t = fsigm(c2[n*625   + (r - 12500)]);
        g_t[j]   = t;
        g_xc0[j] = cutval(0.5f, t);
    }
}

// ---------------- pass 1: filtered fine histogram ----------------
template<int HW, bool VEC>
__device__ __forceinline__ void scan_hist(int e, float4 xv, const float* __restrict__ tb,
                                          const float* __restrict__ cb, unsigned* sh)
{
    float xs[4] = {xv.x, xv.y, xv.z, xv.w};
    if (VEC) {
        int c = e / HW; int hw = e - c*HW;
        float4 cv = *reinterpret_cast<const float4*>(cb + hw);
        float cs[4] = {cv.x, cv.y, cv.z, cv.w};
        #pragma unroll
        for (int j = 0; j < 4; ++j)
            if (xs[j] >= cs[j]) {
                float s = fsigm(xs[j]);
                unsigned key = __float_as_uint(s * tb[hw + j]);
                if (key >= 0x3F000000u) {
                    unsigned b = (key - 0x3F000000u) >> 11;
                    if (b > NB1-1) b = NB1-1;
                    atomicAdd(&sh[b], 1u);
                }
            }
    } else {
        #pragma unroll
        for (int j = 0; j < 4; ++j) {
            int e2 = e + j; int c = e2 / HW; int hw = e2 - c*HW;
            if (xs[j] >= cb[hw]) {
                float s = fsigm(xs[j]);
                unsigned key = __float_as_uint(s * tb[hw]);
                if (key >= 0x3F000000u) {
                    unsigned b = (key - 0x3F000000u) >> 11;
                    if (b > NB1-1) b = NB1-1;
                    atomicAdd(&sh[b], 1u);
                }
            }
        }
    }
}

__global__ __launch_bounds__(256) void pass1_kernel(
    const float* __restrict__ c0, const float* __restrict__ c1, const float* __restrict__ c2)
{
    __shared__ unsigned sh[NB1];
    for (int i = threadIdx.x; i < NB1; i += blockDim.x) sh[i] = 0;
    __syncthreads();

    int n = blockIdx.y, bx = blockIdx.x;
    int lev, b0, nb, vlo, vhi, ctro;
    const float* src;
    if (bx < 48)      { lev = 0; b0 = 0;  nb = 48; vlo = 0;      vhi = 200000; ctro = 0;
                        src = c0 + (size_t)n*800000; }
    else if (bx < 60) { lev = 1; b0 = 48; nb = 12; vlo = 200000; vhi = 250000; ctro = 10000;
                        src = c1 + (size_t)n*200000; }
    else              { lev = 2; b0 = 60; nb = 4;  vlo = 250000; vhi = 262500; ctro = 12500;
                        src = c2 + (size_t)n*50000; }
    const float* tb = g_t   + n*HWPAD + ctro;
    const float* cb = g_xc0 + n*HWPAD + ctro;
    int vstride = nb * blockDim.x;
    int base = vlo * 4;

    for (int v = vlo + (bx - b0)*blockDim.x + threadIdx.x; v < vhi; v += vstride) {
        int e = v*4 - base;
        float4 xv = *reinterpret_cast<const float4*>(src + e);
        if (lev == 0)      scan_hist<10000, true>(e, xv, tb, cb, sh);
        else if (lev == 1) scan_hist<2500, true>(e, xv, tb, cb, sh);
        else               scan_hist<625, false>(e, xv, tb, cb, sh);
    }
    __syncthreads();
    unsigned* gh = g_h1 + (n*3 + lev) * NB1;
    for (int i = threadIdx.x; i < NB1; i += blockDim.x)
        if (sh[i]) atomicAdd(&gh[i], sh[i]);
}

// ---------------- select1: F = floor of bin containing rank-1000 key ----------------
__global__ void select1_kernel()
{
    __shared__ unsigned csum[NB1/32];
    int seg = blockIdx.x, tid = threadIdx.x;
    const unsigned* gh = g_h1 + (size_t)seg * NB1;
    if (tid < NB1/32) {
        unsigned s = 0;
        for (int b = tid*32; b < tid*32 + 32; ++b) s += gh[b];
        csum[tid] = s;
    }
    __syncthreads();
    if (tid == 0) {
        unsigned cum = 0, F = 1; int fb = 1;
        for (int ch = NB1/32 - 1; ch >= 0; --ch) {
            if (cum + csum[ch] >= KSEL) {
                for (int b = ch*32 + 31; ; --b) {
                    cum += gh[b];
                    if (cum >= KSEL) { F = 0x3F000000u | ((unsigned)b << 11); fb = 0; break; }
                }
                break;
            }
            cum += csum[ch];
        }
        g_F[seg] = F; g_fb[seg] = fb;
    }
}

// ---------------- fallback: full coarse histogram + select (normally no-op) ----------
__global__ __launch_bounds__(256) void fb_hist_kernel(
    const float* __restrict__ c0, const float* __restrict__ c1, const float* __restrict__ c2)
{
    int n = blockIdx.y, bx = blockIdx.x;
    int lev, b0, nb, vlo, vhi, ctro;
    const float* src;
    if (bx < 48)      { lev = 0; b0 = 0;  nb = 48; vlo = 0;      vhi = 200000; ctro = 0;
                        src = c0 + (size_t)n*800000; }
    else if (bx < 60) { lev = 1; b0 = 48; nb = 12; vlo = 200000; vhi = 250000; ctro = 10000;
                        src = c1 + (size_t)n*200000; }
    else              { lev = 2; b0 = 60; nb = 4;  vlo = 250000; vhi = 262500; ctro = 12500;
                        src = c2 + (size_t)n*50000; }
    int seg = n*3 + lev;
    if (!g_fb[seg]) return;

    __shared__ unsigned sh[2048];
    for (int i = threadIdx.x; i < 2048; i += blockDim.x) sh[i] = 0;
    __syncthreads();
    const float* tb = g_t + n*HWPAD + ctro;
    int HW = lev == 0 ? 10000 : (lev == 1 ? 2500 : 625);
    int vstride = nb * blockDim.x;
    int base = vlo * 4;
    for (int v = vlo + (bx - b0)*blockDim.x + threadIdx.x; v < vhi; v += vstride) {
        int e = v*4 - base;
        float4 xv = *reinterpret_cast<const float4*>(src + e);
        float xs[4] = {xv.x, xv.y, xv.z, xv.w};
        #pragma unroll
        for (int j = 0; j < 4; ++j) {
            int e2 = e + j; int c = e2 / HW; int hw = e2 - c*HW;
            float s = fsigm(xs[j]);
            if (s > 0.05f) {
                unsigned key = __float_as_uint(s * tb[hw]);
                if (key) atomicAdd(&sh[key >> 21], 1u);
            }
        }
    }
    __syncthreads();
    unsigned* gh = g_h2 + (size_t)seg * 2048;
    for (int i = threadIdx.x; i < 2048; i += blockDim.x)
        if (sh[i]) atomicAdd(&gh[i], sh[i]);
}

__global__ void fb_select_kernel()
{
    int seg = blockIdx.x;
    if (!g_fb[seg]) return;
    __shared__ unsigned csum[64];
    int tid = threadIdx.x;
    const unsigned* gh = g_h2 + (size_t)seg * 2048;
    if (tid < 64) {
        unsigned s = 0;
        for (int b = tid*32; b < tid*32 + 32; ++b) s += gh[b];
        csum[tid] = s;
    }
    __syncthreads();
    if (tid == 0) {
        unsigned cum = 0, F = 1;
        for (int ch = 63; ch >= 0; --ch) {
            if (cum + csum[ch] >= KSEL) {
                for (int b = ch*32 + 31; ; --b) {
                    cum += gh[b];
                    if (cum >= KSEL) { F = ((unsigned)b) << 21; if (F == 0) F = 1; break; }
                }
                break;
            }
            cum += csum[ch];
        }
        g_F[seg] = F;
    }
}

// ---------------- xcutF: per-location collect cutoff ----------------
__global__ void xcutF_kernel()
{
    int i0 = blockIdx.x * blockDim.x + threadIdx.x;
    int st = gridDim.x * blockDim.x;
    for (int j = i0; j < NIMG*HWPAD; j += st) {
        int n = j / HWPAD, r = j - n * HWPAD;
        if (r >= HWTOT) { g_xcF[j] = FLT_MAX; continue; }
        int lev = r < 10000 ? 0 : (r < 12500 ? 1 : 2);
        float Fv = __uint_as_float(g_F[n*3 + lev]);
        g_xcF[j] = cutval(Fv, g_t[j]);
    }
}

// ---------------- collect: filtered exact append ----------------
template<int HW, bool VEC>
__device__ __forceinline__ void scan_collect(int e, float4 xv, const float* __restrict__ tb,
                                             const float* __restrict__ cb, unsigned F, int seg,
                                             unsigned lane)
{
    float xs[4] = {xv.x, xv.y, xv.z, xv.w};
    float cs[4];
    int hwb = 0;
    if (VEC) {
        int c = e / HW; hwb = e - c*HW;
        float4 cv = *reinterpret_cast<const float4*>(cb + hwb);
        cs[0] = cv.x; cs[1] = cv.y; cs[2] = cv.z; cs[3] = cv.w;
    }
    #pragma unroll
    for (int j = 0; j < 4; ++j) {
        bool take = false; unsigned key = 0;
        int hw;
        if (VEC) hw = hwb + j;
        else { int e2 = e + j; int c = e2 / HW; hw = e2 - c*HW; }
        float cut = VEC ? cs[j] : cb[hw];
        if (xs[j] >= cut) {
            float s = fsigm(xs[j]);
            key = (s > 0.05f) ? __float_as_uint(s * tb[hw]) : 0u;
            take = key >= F;
        }
        unsigned mask = __activemask();
        unsigned bal = __ballot_sync(mask, take);
        if (take) {
            int leader = __ffs(bal) - 1;
            unsigned rank = __popc(bal & ((1u << lane) - 1u));
            unsigned basep = 0;
            if ((int)lane == leader)
                basep = atomicAdd(&g_colcnt[seg], (unsigned)__popc(bal));
            basep = __shfl_sync(bal, basep, leader);
            unsigned idx = basep + rank;
            if (idx < CAP) {
                g_colkey[(size_t)seg*CAP + idx] = key;
                g_colpos[(size_t)seg*CAP + idx] = (unsigned)(e + j);
            }
        }
    }
}

__global__ __launch_bounds__(256) void collect_kernel(
    const float* __restrict__ c0, const float* __restrict__ c1, const float* __restrict__ c2)
{
    int n = blockIdx.y, bx = blockIdx.x;
    int lev, b0, nb, vlo, vhi, ctro;
    const float* src;
    if (bx < 48)      { lev = 0; b0 = 0;  nb = 48; vlo = 0;      vhi = 200000; ctro = 0;
                        src = c0 + (size_t)n*800000; }
    else if (bx < 60) { lev = 1; b0 = 48; nb = 12; vlo = 200000; vhi = 250000; ctro = 10000;
                        src = c1 + (size_t)n*200000; }
    else              { lev = 2; b0 = 60; nb = 4;  vlo = 250000; vhi = 262500; ctro = 12500;
                        src = c2 + (size_t)n*50000; }
    int seg = n*3 + lev;
    unsigned F = g_F[seg];
    const float* tb = g_t   + n*HWPAD + ctro;
    const float* cb = g_xcF + n*HWPAD + ctro;
    int vstride = nb * blockDim.x;
    int base = vlo * 4;
    unsigned lane = threadIdx.x & 31;

    for (int v = vlo + (bx - b0)*blockDim.x + threadIdx.x; v < vhi; v += vstride) {
        int e = v*4 - base;
        float4 xv = *reinterpret_cast<const float4*>(src + e);
        if (lev == 0)      scan_collect<10000, true>(e, xv, tb, cb, F, seg, lane);
        else if (lev == 1) scan_collect<2500, true>(e, xv, tb, cb, F, seg, lane);
        else               scan_collect<625, false>(e, xv, tb, cb, F, seg, lane);
    }
}

// ---------------- block-level histogram select (descending) ----------------
__device__ __forceinline__ void bsel(unsigned* sh, int nb, unsigned target,
                                     int* r_bin, unsigned* r_krem)
{
    __shared__ unsigned gsum[64];
    int tid = threadIdx.x;
    int ngroups = nb / 32;
    if (tid < ngroups) {
        unsigned s = 0;
        for (int j = 0; j < 32; ++j) s += sh[tid*32 + j];
        gsum[tid] = s;
    }
    __syncthreads();
    if (tid == 0) {
        unsigned cum = 0;
        *r_bin = 0; *r_krem = target;
        for (int g = ngroups - 1; g >= 0; --g) {
            if (cum + gsum[g] >= target) {
                for (int b = g*32 + 31; b >= g*32; --b) {
                    if (cum + sh[b] >= target) { *r_bin = b; *r_krem = target - cum; return; }
                    cum += sh[b];
                }
            }
            cum += gsum[g];
        }
    }
}

// ---------------- seg_select: exact top-1000 within collected list + decode ------------
__global__ void seg_select_kernel(const float* __restrict__ r0, const float* __restrict__ r1,
                                  const float* __restrict__ r2, const float* __restrict__ l0,
                                  const float* __restrict__ l1, const float* __restrict__ l2)
{
    __shared__ unsigned sh[2048];
    __shared__ int s_bin; __shared__ unsigned s_krem;
    __shared__ unsigned s_T, s_allow, s_emit, s_tie;
    int seg = blockIdx.x;
    int n = seg / 3, lev = seg % 3;
    unsigned mraw = g_colcnt[seg];
    int m = (int)(mraw < CAP ? mraw : CAP);
    const unsigned* keys = g_colkey + (size_t)seg*CAP;
    const unsigned* poss = g_colpos + (size_t)seg*CAP;
    int tid = threadIdx.x;

    if (tid == 0) { s_emit = 0; s_tie = 0; }

    if (m <= KSEL) {
        if (tid == 0) { s_T = 0; s_allow = 0; }
        __syncthreads();
    } else {
        for (int i = tid; i < 2048; i += blockDim.x) sh[i] = 0;
        __syncthreads();
        for (int i = tid; i < m; i += blockDim.x)
            atomicAdd(&sh[keys[i] >> 21], 1u);
        __syncthreads();
        bsel(sh, 2048, KSEL, &s_bin, &s_krem);
        __syncthreads();
        unsigned b1 = (unsigned)s_bin, want = s_krem;
        __syncthreads();
        for (int i = tid; i < 2048; i += blockDim.x) sh[i] = 0;
        __syncthreads();
        for (int i = tid; i < m; i += blockDim.x) {
            unsigned key = keys[i];
            if ((key >> 21) == b1) atomicAdd(&sh[(key >> 10) & 0x7FF], 1u);
        }
        __syncthreads();
        bsel(sh, 2048, want, &s_bin, &s_krem);
        __syncthreads();
        unsigned b2 = (unsigned)s_bin; want = s_krem;
        unsigned pfx2 = (b1 << 11) | b2;
        __syncthreads();
        for (int i = tid; i < 1024; i += blockDim.x) sh[i] = 0;
        __syncthreads();
        for (int i = tid; i < m; i += blockDim.x) {
            unsigned key = keys[i];
            if ((key >> 10) == pfx2) atomicAdd(&sh[key & 0x3FF], 1u);
        }
        __syncthreads();
        bsel(sh, 1024, want, &s_bin, &s_krem);
        __syncthreads();
        if (tid == 0) { s_T = (pfx2 << 10) | (unsigned)s_bin; s_allow = s_krem; }
        __syncthreads();
    }
    unsigned T = s_T, allow = s_allow;

    const float* rg; const float* lc; int HW; float sf;
    if (lev == 0)      { rg = r0 + (size_t)n*40000; lc = l0; HW = 10000; sf = 8.0f; }
    else if (lev == 1) { rg = r1 + (size_t)n*10000; lc = l1; HW = 2500;  sf = 16.0f; }
    else               { rg = r2 + (size_t)n*2500;  lc = l2; HW = 625;   sf = 32.0f; }

    for (int i = tid; i < m; i += blockDim.x) {
        unsigned key = keys[i];
        bool take;
        if (m <= KSEL) take = true;
        else {
            take = key > T;
            if (!take && key == T && allow) take = (atomicAdd(&s_tie, 1u) < allow);
        }
        if (!take) continue;
        unsigned slot = atomicAdd(&s_emit, 1u);
        unsigned pos = poss[i];
        int c = (int)pos / HW, hw = (int)pos - c * HW;
        float l = rg[hw]        * sf;
        float t = rg[HW + hw]   * sf;
        float r = rg[2*HW + hw] * sf;
        float b = rg[3*HW + hw] * sf;
        float x = lc[2*hw], y = lc[2*hw + 1];
        float x1 = fminf(fmaxf(x - l, 0.f), 800.f);
        float y1 = fminf(fmaxf(y - t, 0.f), 800.f);
        float x2 = fminf(fmaxf(x + r, 0.f), 800.f);
        float y2 = fminf(fmaxf(y + b, 0.f), 800.f);
        int g = n * NCAND + lev * KSEL + (int)slot;
        g_cbox[g] = make_float4(x1, y1, x2, y2);
        g_csc[g]  = sqrtf(__uint_as_float(key));
        g_ccls[g] = c + 1;
    }
}

// ---------------- greedy NMS: all loop state in smem/registers ----------------
#define NTH 512
#define KC  6    // 512*6 = 3072 >= NCAND
__global__ __launch_bounds__(NTH) void nms_kernel(float* __restrict__ out)
{
    extern __shared__ unsigned char smraw[];
    float* ox1 = (float*)smraw;          // offset coords (for IoU)
    float* oy1 = ox1 + NCAND;
    float* ox2 = oy1 + NCAND;
    float* oy2 = ox2 + NCAND;
    float* oar = oy2 + NCAND;
    float* ex1 = oar + NCAND;            // exact output coords
    float* ey1 = ex1 + NCAND;
    float* ex2 = ey1 + NCAND;
    float* ey2 = ex2 + NCAND;
    int*   scl = (int*)(ey2 + NCAND);

    __shared__ float rs[NTH/32]; __shared__ int ri[NTH/32];
    __shared__ float sB; __shared__ int sI;

    int n = blockIdx.x;
    int tid = threadIdx.x;
    int lane = tid & 31, wid = tid >> 5;

    float sc[KC], bx1[KC], by1[KC], bx2[KC], by2[KC], ba[KC];
    #pragma unroll
    for (int k = 0; k < KC; ++k) {
        int i = tid + k * NTH;
        float s = -2.0f, x1 = 0.f, y1 = 0.f, x2 = 0.f, y2 = 0.f, a = 0.f;
        if (i < NCAND) {
            s = g_csc[n*NCAND + i];
            float4 b = g_cbox[n*NCAND + i];
            int c = g_ccls[n*NCAND + i];
            if (s > 0.f) {
                float off = (float)c * 4096.0f;
                x1 = b.x + off; y1 = b.y + off; x2 = b.z + off; y2 = b.w + off;
                a = (x2 - x1) * (y2 - y1);
            } else s = -1.0f;
            ox1[i] = x1; oy1[i] = y1; ox2[i] = x2; oy2[i] = y2; oar[i] = a;
            ex1[i] = b.x; ey1[i] = b.y; ex2[i] = b.z; ey2[i] = b.w;
            scl[i] = c;
        }
        sc[k] = s; bx1[k] = x1; by1[k] = y1; bx2[k] = x2; by2[k] = y2; ba[k] = a;
    }
    __syncthreads();

    for (int it = 0; it < NPICK; ++it) {
        float bs = -3.0f; int bi = 0x7FFFFFFF;
        #pragma unroll
        for (int k = 0; k < KC; ++k)
            if (sc[k] > bs) { bs = sc[k]; bi = tid + k*NTH; }
        #pragma unroll
        for (int o = 16; o; o >>= 1) {
            float s2 = __shfl_down_sync(0xFFFFFFFFu, bs, o);
            int   i2 = __shfl_down_sync(0xFFFFFFFFu, bi, o);
            if (s2 > bs || (s2 == bs && i2 < bi)) { bs = s2; bi = i2; }
        }
        if (lane == 0) { rs[wid] = bs; ri[wid] = bi; }
        __syncthreads();
        if (wid == 0) {
            float s = (lane < NTH/32) ? rs[lane] : -3.0f;
            int   b = (lane < NTH/32) ? ri[lane] : 0x7FFFFFFF;
            #pragma unroll
            for (int o = 8; o; o >>= 1) {
                float s2 = __shfl_down_sync(0xFFFFFFFFu, s, o);
                int   b2 = __shfl_down_sync(0xFFFFFFFFu, b, o);
                if (s2 > s || (s2 == s && b2 < b)) { s = s2; b = b2; }
            }
            if (lane == 0) { sB = s; sI = b; }
        }
        __syncthreads();
        float pbs = sB; int pbi = sI;
        bool keep = pbs > 0.0f;

        if (tid < 7) {
            int row = n * NPICK + it;
            float val = 0.f;
            if (keep) {
                if (tid == 0) val = ex1[pbi];
                else if (tid == 1) val = ey1[pbi];
                else if (tid == 2) val = ex2[pbi];
                else if (tid == 3) val = ey2[pbi];
                else if (tid == 4) val = pbs;
                else if (tid == 5) val = (float)scl[pbi];
                else               val = 1.0f;
            }
            if (tid < 4)       out[OFS_BOX + row*4 + tid] = val;
            else if (tid == 4) out[OFS_SC + row] = val;
            else if (tid == 5) out[OFS_CL + row] = val;
            else               out[OFS_KP + row] = val;
        }

        float px1 = ox1[pbi], py1 = oy1[pbi], px2 = ox2[pbi], py2 = oy2[pbi], pa = oar[pbi];
        #pragma unroll
        for (int k = 0; k < KC; ++k) {
            if (tid + k*NTH == pbi) { sc[k] = -1.0f; continue; }
            float xx1 = fmaxf(px1, bx1[k]);
            float yy1 = fmaxf(py1, by1[k]);
            float xx2 = fminf(px2, bx2[k]);
            float yy2 = fminf(py2, by2[k]);
            float inter = fmaxf(xx2 - xx1, 0.f) * fmaxf(yy2 - yy1, 0.f);
            float iou = inter / (ba[k] + pa - inter + 1e-9f);
            if (iou > 0.6f && sc[k] > -1.5f) sc[k] = -1.0f;
        }
    }
}

// ---------------- launch ----------------
extern "C" void kernel_launch(void* const* d_in, const int* in_sizes, int n_in,
                              void* d_out, int out_size)
{
    const float *loc0, *loc1, *loc2, *cls0, *cls1, *cls2;
    const float *reg0, *reg1, *reg2, *ctr0, *ctr1, *ctr2;
    if (in_sizes[1] == 16 * 80 * 10000) {
        loc0 = (const float*)d_in[0];  cls0 = (const float*)d_in[1];
        reg0 = (const float*)d_in[2];  ctr0 = (const float*)d_in[3];
        loc1 = (const float*)d_in[4];  cls1 = (const float*)d_in[5];
        reg1 = (const float*)d_in[6];  ctr1 = (const float*)d_in[7];
        loc2 = (const float*)d_in[8];  cls2 = (const float*)d_in[9];
        reg2 = (const float*)d_in[10]; ctr2 = (const float*)d_in[11];
    } else {
        loc0 = (const float*)d_in[0];  loc1 = (const float*)d_in[1];  loc2 = (const float*)d_in[2];
        cls0 = (const float*)d_in[3];  cls1 = (const float*)d_in[4];  cls2 = (const float*)d_in[5];
        reg0 = (const float*)d_in[6];  reg1 = (const float*)d_in[7];  reg2 = (const float*)d_in[8];
        ctr0 = (const float*)d_in[9];  ctr1 = (const float*)d_in[10]; ctr2 = (const float*)d_in[11];
    }
    float* out = (float*)d_out;

    const int NMS_SMEM = 10 * NCAND * 4;
    cudaFuncSetAttribute(nms_kernel, cudaFuncAttributeMaxDynamicSharedMemorySize, NMS_SMEM);

    init_kernel<<<416, 256>>>(ctr0, ctr1, ctr2);
    pass1_kernel<<<dim3(64, NIMG), 256>>>(cls0, cls1, cls2);
    select1_kernel<<<NIMG*3, 256>>>();
    fb_hist_kernel<<<dim3(64, NIMG), 256>>>(cls0, cls1, cls2);
    fb_select_kernel<<<NIMG*3, 256>>>();
    xcutF_kernel<<<256, 256>>>();
    collect_kernel<<<dim3(64, NIMG), 256>>>(cls0, cls1, cls2);
    seg_select_kernel<<<NIMG*3, 256>>>(reg0, reg1, reg2, loc0, loc1, loc2);
    nms_kernel<<<NIMG, NTH, NMS_SMEM>>>(out);
}

// round 15
// speedup vs baseline: 2.6081x; 1.9288x over previous
#include <cuda_runtime.h>
#include <math.h>
#include <float.h>

#define NIMG   16
#define KSEL   1000
#define NCAND  3000
#define NPICK  100
#define HWTOT  13125
#define HWPAD  13128
#define MTOT   1050000
#define CAP    131072
#define NB1    4096

// Output layout (float32, concatenated tuple: boxes, scores, classes, keep)
#define OFS_BOX 0
#define OFS_SC  (NIMG*NPICK*4)
#define OFS_CL  (OFS_SC + NIMG*NPICK)
#define OFS_KP  (OFS_CL + NIMG*NPICK)

// ---------------- scratch (device globals, no allocation) ----------------
__device__ float    g_t[NIMG*HWPAD];      // sigmoid(ctr) per location
__device__ float    g_xc0[NIMG*HWPAD];    // static cutoff: x >= xc0 => key may be >= 0.5
__device__ float    g_xcF[NIMG*HWPAD];    // per-segment cutoff for F
__device__ unsigned g_h1[NIMG*3*NB1];     // fine hist over [0.5,1)
__device__ unsigned g_h2[NIMG*3*2048];    // fallback coarse hist
__device__ unsigned g_F[NIMG*3];
__device__ unsigned g_fb[NIMG*3];
__device__ unsigned g_colcnt[NIMG*3];
__device__ unsigned g_colkey[(size_t)NIMG*3*CAP];
__device__ unsigned g_colpos[(size_t)NIMG*3*CAP];
__device__ float4   g_cbox[NIMG*NCAND];
__device__ float    g_csc[NIMG*NCAND];
__device__ int      g_ccls[NIMG*NCAND];

__device__ __forceinline__ float fsigm(float x) { return __fdividef(1.0f, 1.0f + __expf(-x)); }

// Conservative x-cutoff: every element whose exact key (= fl(fsigm(x)*t)) can be
// >= Fv satisfies x >= cutval(Fv,t).
__device__ __forceinline__ float cutval(float Fv, float t)
{
    if (!(t > Fv)) return (t == Fv) ? 16.0f : FLT_MAX;
    float r = Fv / (t - Fv);
    if (r > 1.0e6f) return -1000.0f;
    return logf(r) - (0.05f + 5e-6f * r);
}

// ---------------- init: tables + zero scratch ----------------
__global__ void init_kernel(const float* __restrict__ c0, const float* __restrict__ c1,
                            const float* __restrict__ c2)
{
    int i0 = blockIdx.x * blockDim.x + threadIdx.x;
    int st = gridDim.x * blockDim.x;
    for (int j = i0; j < NIMG*3*NB1; j += st) g_h1[j] = 0;
    for (int j = i0; j < NIMG*3*2048; j += st) g_h2[j] = 0;
    for (int j = i0; j < NIMG*3; j += st) g_colcnt[j] = 0;
    for (int j = i0; j < NIMG*NCAND; j += st) {
        g_csc[j] = -1.0f; g_ccls[j] = 0;
        g_cbox[j] = make_float4(0.f, 0.f, 0.f, 0.f);
    }
    for (int j = i0; j < NIMG*HWPAD; j += st) {
        int n = j / HWPAD, r = j - n * HWPAD;
        float t = 0.0f;
        if (r < 10000)      t = fsigm(c0[n*10000 + r]);
        else if (r < 12500) t = fsigm(c1[n*2500  + (r - 10000)]);
        else if (r < HWTOT) t = fsigm(c2[n*625   + (r - 12500)]);
        g_t[j]   = t;
        g_xc0[j] = cutval(0.5f, t);
    }
}

// ---------------- pass 1: filtered fine histogram ----------------
template<int HW, bool VEC>
__device__ __forceinline__ void scan_hist(int e, float4 xv, const float* __restrict__ tb,
                                          const float* __restrict__ cb, unsigned* sh)
{
    float xs[4] = {xv.x, xv.y, xv.z, xv.w};
    if (VEC) {
        int c = e / HW; int hw = e - c*HW;
        float4 cv = *reinterpret_cast<const float4*>(cb + hw);
        float cs[4] = {cv.x, cv.y, cv.z, cv.w};
        #pragma unroll
        for (int j = 0; j < 4; ++j)
            if (xs[j] >= cs[j]) {
                float s = fsigm(xs[j]);
                unsigned key = __float_as_uint(s * tb[hw + j]);
                if (key >= 0x3F000000u) {
                    unsigned b = (key - 0x3F000000u) >> 11;
                    if (b > NB1-1) b = NB1-1;
                    atomicAdd(&sh[b], 1u);
                }
            }
    } else {
        #pragma unroll
        for (int j = 0; j < 4; ++j) {
            int e2 = e + j; int c = e2 / HW; int hw = e2 - c*HW;
            if (xs[j] >= cb[hw]) {
                float s = fsigm(xs[j]);
                unsigned key = __float_as_uint(s * tb[hw]);
                if (key >= 0x3F000000u) {
                    unsigned b = (key - 0x3F000000u) >> 11;
                    if (b > NB1-1) b = NB1-1;
                    atomicAdd(&sh[b], 1u);
                }
            }
        }
    }
}

__global__ __launch_bounds__(256) void pass1_kernel(
    const float* __restrict__ c0, const float* __restrict__ c1, const float* __restrict__ c2)
{
    __shared__ unsigned sh[NB1];
    for (int i = threadIdx.x; i < NB1; i += blockDim.x) sh[i] = 0;
    __syncthreads();

    int n = blockIdx.y, bx = blockIdx.x;
    int lev, b0, nb, vlo, vhi, ctro;
    const float* src;
    if (bx < 48)      { lev = 0; b0 = 0;  nb = 48; vlo = 0;      vhi = 200000; ctro = 0;
                        src = c0 + (size_t)n*800000; }
    else if (bx < 60) { lev = 1; b0 = 48; nb = 12; vlo = 200000; vhi = 250000; ctro = 10000;
                        src = c1 + (size_t)n*200000; }
    else              { lev = 2; b0 = 60; nb = 4;  vlo = 250000; vhi = 262500; ctro = 12500;
                        src = c2 + (size_t)n*50000; }
    const float* tb = g_t   + n*HWPAD + ctro;
    const float* cb = g_xc0 + n*HWPAD + ctro;
    int vstride = nb * blockDim.x;
    int base = vlo * 4;

    for (int v = vlo + (bx - b0)*blockDim.x + threadIdx.x; v < vhi; v += vstride) {
        int e = v*4 - base;
        float4 xv = *reinterpret_cast<const float4*>(src + e);
        if (lev == 0)      scan_hist<10000, true>(e, xv, tb, cb, sh);
        else if (lev == 1) scan_hist<2500, true>(e, xv, tb, cb, sh);
        else               scan_hist<625, false>(e, xv, tb, cb, sh);
    }
    __syncthreads();
    unsigned* gh = g_h1 + (n*3 + lev) * NB1;
    for (int i = threadIdx.x; i < NB1; i += blockDim.x)
        if (sh[i]) atomicAdd(&gh[i], sh[i]);
}

// ---------------- select1: F = floor of bin containing rank-1000 key ----------------
__global__ void select1_kernel()
{
    __shared__ unsigned csum[NB1/32];
    int seg = blockIdx.x, tid = threadIdx.x;
    const unsigned* gh = g_h1 + (size_t)seg * NB1;
    if (tid < NB1/32) {
        unsigned s = 0;
        for (int b = tid*32; b < tid*32 + 32; ++b) s += gh[b];
        csum[tid] = s;
    }
    __syncthreads();
    if (tid == 0) {
        unsigned cum = 0, F = 1; int fb = 1;
        for (int ch = NB1/32 - 1; ch >= 0; --ch) {
            if (cum + csum[ch] >= KSEL) {
                for (int b = ch*32 + 31; ; --b) {
                    cum += gh[b];
                    if (cum >= KSEL) { F = 0x3F000000u | ((unsigned)b << 11); fb = 0; break; }
                }
                break;
            }
            cum += csum[ch];
        }
        g_F[seg] = F; g_fb[seg] = fb;
    }
}

// ---------------- fallback: full coarse histogram + select (normally no-op) ----------
__global__ __launch_bounds__(256) void fb_hist_kernel(
    const float* __restrict__ c0, const float* __restrict__ c1, const float* __restrict__ c2)
{
    int n = blockIdx.y, bx = blockIdx.x;
    int lev, b0, nb, vlo, vhi, ctro;
    const float* src;
    if (bx < 48)      { lev = 0; b0 = 0;  nb = 48; vlo = 0;      vhi = 200000; ctro = 0;
                        src = c0 + (size_t)n*800000; }
    else if (bx < 60) { lev = 1; b0 = 48; nb = 12; vlo = 200000; vhi = 250000; ctro = 10000;
                        src = c1 + (size_t)n*200000; }
    else              { lev = 2; b0 = 60; nb = 4;  vlo = 250000; vhi = 262500; ctro = 12500;
                        src = c2 + (size_t)n*50000; }
    int seg = n*3 + lev;
    if (!g_fb[seg]) return;

    __shared__ unsigned sh[2048];
    for (int i = threadIdx.x; i < 2048; i += blockDim.x) sh[i] = 0;
    __syncthreads();
    const float* tb = g_t + n*HWPAD + ctro;
    int HW = lev == 0 ? 10000 : (lev == 1 ? 2500 : 625);
    int vstride = nb * blockDim.x;
    int base = vlo * 4;
    for (int v = vlo + (bx - b0)*blockDim.x + threadIdx.x; v < vhi; v += vstride) {
        int e = v*4 - base;
        float4 xv = *reinterpret_cast<const float4*>(src + e);
        float xs[4] = {xv.x, xv.y, xv.z, xv.w};
        #pragma unroll
        for (int j = 0; j < 4; ++j) {
            int e2 = e + j; int c = e2 / HW; int hw = e2 - c*HW;
            float s = fsigm(xs[j]);
            if (s > 0.05f) {
                unsigned key = __float_as_uint(s * tb[hw]);
                if (key) atomicAdd(&sh[key >> 21], 1u);
            }
        }
    }
    __syncthreads();
    unsigned* gh = g_h2 + (size_t)seg * 2048;
    for (int i = threadIdx.x; i < 2048; i += blockDim.x)
        if (sh[i]) atomicAdd(&gh[i], sh[i]);
}

__global__ void fb_select_kernel()
{
    int seg = blockIdx.x;
    if (!g_fb[seg]) return;
    __shared__ unsigned csum[64];
    int tid = threadIdx.x;
    const unsigned* gh = g_h2 + (size_t)seg * 2048;
    if (tid < 64) {
        unsigned s = 0;
        for (int b = tid*32; b < tid*32 + 32; ++b) s += gh[b];
        csum[tid] = s;
    }
    __syncthreads();
    if (tid == 0) {
        unsigned cum = 0, F = 1;
        for (int ch = 63; ch >= 0; --ch) {
            if (cum + csum[ch] >= KSEL) {
                for (int b = ch*32 + 31; ; --b) {
                    cum += gh[b];
                    if (cum >= KSEL) { F = ((unsigned)b) << 21; if (F == 0) F = 1; break; }
                }
                break;
            }
            cum += csum[ch];
        }
        g_F[seg] = F;
    }
}

// ---------------- xcutF: per-location collect cutoff ----------------
__global__ void xcutF_kernel()
{
    int i0 = blockIdx.x * blockDim.x + threadIdx.x;
    int st = gridDim.x * blockDim.x;
    for (int j = i0; j < NIMG*HWPAD; j += st) {
        int n = j / HWPAD, r = j - n * HWPAD;
        if (r >= HWTOT) { g_xcF[j] = FLT_MAX; continue; }
        int lev = r < 10000 ? 0 : (r < 12500 ? 1 : 2);
        float Fv = __uint_as_float(g_F[n*3 + lev]);
        g_xcF[j] = cutval(Fv, g_t[j]);
    }
}

// ---------------- collect: filtered exact append ----------------
template<int HW, bool VEC>
__device__ __forceinline__ void scan_collect(int e, float4 xv, const float* __restrict__ tb,
                                             const float* __restrict__ cb, unsigned F, int seg,
                                             unsigned lane)
{
    float xs[4] = {xv.x, xv.y, xv.z, xv.w};
    float cs[4];
    int hwb = 0;
    if (VEC) {
        int c = e / HW; hwb = e - c*HW;
        float4 cv = *reinterpret_cast<const float4*>(cb + hwb);
        cs[0] = cv.x; cs[1] = cv.y; cs[2] = cv.z; cs[3] = cv.w;
    }
    #pragma unroll
    for (int j = 0; j < 4; ++j) {
        bool take = false; unsigned key = 0;
        int hw;
        if (VEC) hw = hwb + j;
        else { int e2 = e + j; int c = e2 / HW; hw = e2 - c*HW; }
        float cut = VEC ? cs[j] : cb[hw];
        if (xs[j] >= cut) {
            float s = fsigm(xs[j]);
            key = (s > 0.05f) ? __float_as_uint(s * tb[hw]) : 0u;
            take = key >= F;
        }
        unsigned mask = __activemask();
        unsigned bal = __ballot_sync(mask, take);
        if (take) {
            int leader = __ffs(bal) - 1;
            unsigned rank = __popc(bal & ((1u << lane) - 1u));
            unsigned basep = 0;
            if ((int)lane == leader)
                basep = atomicAdd(&g_colcnt[seg], (unsigned)__popc(bal));
            basep = __shfl_sync(bal, basep, leader);
            unsigned idx = basep + rank;
            if (idx < CAP) {
                g_colkey[(size_t)seg*CAP + idx] = key;
                g_colpos[(size_t)seg*CAP + idx] = (unsigned)(e + j);
            }
        }
    }
}

__global__ __launch_bounds__(256) void collect_kernel(
    const float* __restrict__ c0, const float* __restrict__ c1, const float* __restrict__ c2)
{
    int n = blockIdx.y, bx = blockIdx.x;
    int lev, b0, nb, vlo, vhi, ctro;
    const float* src;
    if (bx < 48)      { lev = 0; b0 = 0;  nb = 48; vlo = 0;      vhi = 200000; ctro = 0;
                        src = c0 + (size_t)n*800000; }
    else if (bx < 60) { lev = 1; b0 = 48; nb = 12; vlo = 200000; vhi = 250000; ctro = 10000;
                        src = c1 + (size_t)n*200000; }
    else              { lev = 2; b0 = 60; nb = 4;  vlo = 250000; vhi = 262500; ctro = 12500;
                        src = c2 + (size_t)n*50000; }
    int seg = n*3 + lev;
    unsigned F = g_F[seg];
    const float* tb = g_t   + n*HWPAD + ctro;
    const float* cb = g_xcF + n*HWPAD + ctro;
    int vstride = nb * blockDim.x;
    int base = vlo * 4;
    unsigned lane = threadIdx.x & 31;

    for (int v = vlo + (bx - b0)*blockDim.x + threadIdx.x; v < vhi; v += vstride) {
        int e = v*4 - base;
        float4 xv = *reinterpret_cast<const float4*>(src + e);
        if (lev == 0)      scan_collect<10000, true>(e, xv, tb, cb, F, seg, lane);
        else if (lev == 1) scan_collect<2500, true>(e, xv, tb, cb, F, seg, lane);
        else               scan_collect<625, false>(e, xv, tb, cb, F, seg, lane);
    }
}

// ---------------- block-level histogram select (descending) ----------------
__device__ __forceinline__ void bsel(unsigned* sh, int nb, unsigned target,
                                     int* r_bin, unsigned* r_krem)
{
    __shared__ unsigned gsum[64];
    int tid = threadIdx.x;
    int ngroups = nb / 32;
    if (tid < ngroups) {
        unsigned s = 0;
        for (int j = 0; j < 32; ++j) s += sh[tid*32 + j];
        gsum[tid] = s;
    }
    __syncthreads();
    if (tid == 0) {
        unsigned cum = 0;
        *r_bin = 0; *r_krem = target;
        for (int g = ngroups - 1; g >= 0; --g) {
            if (cum + gsum[g] >= target) {
                for (int b = g*32 + 31; b >= g*32; --b) {
                    if (cum + sh[b] >= target) { *r_bin = b; *r_krem = target - cum; return; }
                    cum += sh[b];
                }
            }
            cum += gsum[g];
        }
    }
}

// ---------------- seg_select: exact top-1000 within collected list + decode ------------
__global__ void seg_select_kernel(const float* __restrict__ r0, const float* __restrict__ r1,
                                  const float* __restrict__ r2, const float* __restrict__ l0,
                                  const float* __restrict__ l1, const float* __restrict__ l2)
{
    __shared__ unsigned sh[2048];
    __shared__ int s_bin; __shared__ unsigned s_krem;
    __shared__ unsigned s_T, s_allow, s_emit, s_tie;
    int seg = blockIdx.x;
    int n = seg / 3, lev = seg % 3;
    unsigned mraw = g_colcnt[seg];
    int m = (int)(mraw < CAP ? mraw : CAP);
    const unsigned* keys = g_colkey + (size_t)seg*CAP;
    const unsigned* poss = g_colpos + (size_t)seg*CAP;
    int tid = threadIdx.x;

    if (tid == 0) { s_emit = 0; s_tie = 0; }

    if (m <= KSEL) {
        if (tid == 0) { s_T = 0; s_allow = 0; }
        __syncthreads();
    } else {
        for (int i = tid; i < 2048; i += blockDim.x) sh[i] = 0;
        __syncthreads();
        for (int i = tid; i < m; i += blockDim.x)
            atomicAdd(&sh[keys[i] >> 21], 1u);
        __syncthreads();
        bsel(sh, 2048, KSEL, &s_bin, &s_krem);
        __syncthreads();
        unsigned b1 = (unsigned)s_bin, want = s_krem;
        __syncthreads();
        for (int i = tid; i < 2048; i += blockDim.x) sh[i] = 0;
        __syncthreads();
        for (int i = tid; i < m; i += blockDim.x) {
            unsigned key = keys[i];
            if ((key >> 21) == b1) atomicAdd(&sh[(key >> 10) & 0x7FF], 1u);
        }
        __syncthreads();
        bsel(sh, 2048, want, &s_bin, &s_krem);
        __syncthreads();
        unsigned b2 = (unsigned)s_bin; want = s_krem;
        unsigned pfx2 = (b1 << 11) | b2;
        __syncthreads();
        for (int i = tid; i < 1024; i += blockDim.x) sh[i] = 0;
        __syncthreads();
        for (int i = tid; i < m; i += blockDim.x) {
            unsigned key = keys[i];
            if ((key >> 10) == pfx2) atomicAdd(&sh[key & 0x3FF], 1u);
        }
        __syncthreads();
        bsel(sh, 1024, want, &s_bin, &s_krem);
        __syncthreads();
        if (tid == 0) { s_T = (pfx2 << 10) | (unsigned)s_bin; s_allow = s_krem; }
        __syncthreads();
    }
    unsigned T = s_T, allow = s_allow;

    const float* rg; const float* lc; int HW; float sf;
    if (lev == 0)      { rg = r0 + (size_t)n*40000; lc = l0; HW = 10000; sf = 8.0f; }
    else if (lev == 1) { rg = r1 + (size_t)n*10000; lc = l1; HW = 2500;  sf = 16.0f; }
    else               { rg = r2 + (size_t)n*2500;  lc = l2; HW = 625;   sf = 32.0f; }

    for (int i = tid; i < m; i += blockDim.x) {
        unsigned key = keys[i];
        bool take;
        if (m <= KSEL) take = true;
        else {
            take = key > T;
            if (!take && key == T && allow) take = (atomicAdd(&s_tie, 1u) < allow);
        }
        if (!take) continue;
        unsigned slot = atomicAdd(&s_emit, 1u);
        unsigned pos = poss[i];
        int c = (int)pos / HW, hw = (int)pos - c * HW;
        float l = rg[hw]        * sf;
        float t = rg[HW + hw]   * sf;
        float r = rg[2*HW + hw] * sf;
        float b = rg[3*HW + hw] * sf;
        float x = lc[2*hw], y = lc[2*hw + 1];
        float x1 = fminf(fmaxf(x - l, 0.f), 800.f);
        float y1 = fminf(fmaxf(y - t, 0.f), 800.f);
        float x2 = fminf(fmaxf(x + r, 0.f), 800.f);
        float y2 = fminf(fmaxf(y + b, 0.f), 800.f);
        int g = n * NCAND + lev * KSEL + (int)slot;
        g_cbox[g] = make_float4(x1, y1, x2, y2);
        g_csc[g]  = sqrtf(__uint_as_float(key));
        g_ccls[g] = c + 1;
    }
}

// ---------------- greedy NMS (R7 shape: 1024 threads, KC=3; smem-staged outputs) -------
__global__ __launch_bounds__(1024) void nms_kernel(float* __restrict__ out)
{
    extern __shared__ unsigned char smraw[];
    float* sx1 = (float*)smraw;          // offset coords (for IoU)
    float* sy1 = sx1 + NCAND;
    float* sx2 = sy1 + NCAND;
    float* sy2 = sx2 + NCAND;
    float* sar = sy2 + NCAND;
    float* ex1 = sar + NCAND;            // exact output coords
    float* ey1 = ex1 + NCAND;
    float* ex2 = ey1 + NCAND;
    float* ey2 = ex2 + NCAND;
    int*   scl = (int*)(ey2 + NCAND);

    __shared__ float rs[32]; __shared__ int ri[32];
    __shared__ float sB; __shared__ int sI;

    int n = blockIdx.x;
    int tid = threadIdx.x;
    int lane = tid & 31, wid = tid >> 5;

    float sc[3], bx1[3], by1[3], bx2[3], by2[3], ba[3];
    #pragma unroll
    for (int k = 0; k < 3; ++k) {
        int i = tid + k * 1024;
        float s = -2.0f, x1 = 0.f, y1 = 0.f, x2 = 0.f, y2 = 0.f, a = 0.f;
        if (i < NCAND) {
            s = g_csc[n*NCAND + i];
            float4 b = g_cbox[n*NCAND + i];
            int c = g_ccls[n*NCAND + i];
            if (s > 0.f) {
                float off = (float)c * 4096.0f;
                x1 = b.x + off; y1 = b.y + off; x2 = b.z + off; y2 = b.w + off;
                a = (x2 - x1) * (y2 - y1);
            } else s = -1.0f;
            sx1[i] = x1; sy1[i] = y1; sx2[i] = x2; sy2[i] = y2; sar[i] = a;
            ex1[i] = b.x; ey1[i] = b.y; ex2[i] = b.z; ey2[i] = b.w;
            scl[i] = c;
        }
        sc[k] = s; bx1[k] = x1; by1[k] = y1; bx2[k] = x2; by2[k] = y2; ba[k] = a;
    }
    __syncthreads();

    for (int it = 0; it < NPICK; ++it) {
        float bs = -3.0f; int bi = 0x7FFFFFFF;
        #pragma unroll
        for (int k = 0; k < 3; ++k)
            if (sc[k] > bs) { bs = sc[k]; bi = tid + k*1024; }
        #pragma unroll
        for (int o = 16; o; o >>= 1) {
            float s2 = __shfl_down_sync(0xFFFFFFFFu, bs, o);
            int   i2 = __shfl_down_sync(0xFFFFFFFFu, bi, o);
            if (s2 > bs || (s2 == bs && i2 < bi)) { bs = s2; bi = i2; }
        }
        if (lane == 0) { rs[wid] = bs; ri[wid] = bi; }
        __syncthreads();
        if (wid == 0) {
            float s = rs[lane]; int b = ri[lane];
            #pragma unroll
            for (int o = 16; o; o >>= 1) {
                float s2 = __shfl_down_sync(0xFFFFFFFFu, s, o);
                int   b2 = __shfl_down_sync(0xFFFFFFFFu, b, o);
                if (s2 > s || (s2 == s && b2 < b)) { s = s2; b = b2; }
            }
            if (lane == 0) { sB = s; sI = b; }
        }
        __syncthreads();
        float pbs = sB; int pbi = sI;
        bool keep = pbs > 0.0f;

        if (tid < 7) {
            int row = n * NPICK + it;
            float val = 0.f;
            if (keep) {
                if (tid == 0) val = ex1[pbi];
                else if (tid == 1) val = ey1[pbi];
                else if (tid == 2) val = ex2[pbi];
                else if (tid == 3) val = ey2[pbi];
                else if (tid == 4) val = pbs;
                else if (tid == 5) val = (float)scl[pbi];
                else               val = 1.0f;
            }
            if (tid < 4)       out[OFS_BOX + row*4 + tid] = val;
            else if (tid == 4) out[OFS_SC + row] = val;
            else if (tid == 5) out[OFS_CL + row] = val;
            else               out[OFS_KP + row] = val;
        }

        float px1 = sx1[pbi], py1 = sy1[pbi], px2 = sx2[pbi], py2 = sy2[pbi], pa = sar[pbi];
        #pragma unroll
        for (int k = 0; k < 3; ++k) {
            if (tid + k*1024 == pbi) { sc[k] = -1.0f; continue; }
            float xx1 = fmaxf(px1, bx1[k]);
            float yy1 = fmaxf(py1, by1[k]);
            float xx2 = fminf(px2, bx2[k]);
            float yy2 = fminf(py2, by2[k]);
            float inter = fmaxf(xx2 - xx1, 0.f) * fmaxf(yy2 - yy1, 0.f);
            float iou = inter / (ba[k] + pa - inter + 1e-9f);
            if (iou > 0.6f && sc[k] > -1.5f) sc[k] = -1.0f;
        }
    }
}

// ---------------- launch ----------------
extern "C" void kernel_launch(void* const* d_in, const int* in_sizes, int n_in,
                              void* d_out, int out_size)
{
    const float *loc0, *loc1, *loc2, *cls0, *cls1, *cls2;
    const float *reg0, *reg1, *reg2, *ctr0, *ctr1, *ctr2;
    if (in_sizes[1] == 16 * 80 * 10000) {
        loc0 = (const float*)d_in[0];  cls0 = (const float*)d_in[1];
        reg0 = (const float*)d_in[2];  ctr0 = (const float*)d_in[3];
        loc1 = (const float*)d_in[4];  cls1 = (const float*)d_in[5];
        reg1 = (const float*)d_in[6];  ctr1 = (const float*)d_in[7];
        loc2 = (const float*)d_in[8];  cls2 = (const float*)d_in[9];
        reg2 = (const float*)d_in[10]; ctr2 = (const float*)d_in[11];
    } else {
        loc0 = (const float*)d_in[0];  loc1 = (const float*)d_in[1];  loc2 = (const float*)d_in[2];
        cls0 = (const float*)d_in[3];  cls1 = (const float*)d_in[4];  cls2 = (const float*)d_in[5];
        reg0 = (const float*)d_in[6];  reg1 = (const float*)d_in[7];  reg2 = (const float*)d_in[8];
        ctr0 = (const float*)d_in[9];  ctr1 = (const float*)d_in[10]; ctr2 = (const float*)d_in[11];
    }
    float* out = (float*)d_out;

    const int NMS_SMEM = 10 * NCAND * 4;
    cudaFuncSetAttribute(nms_kernel, cudaFuncAttributeMaxDynamicSharedMemorySize, NMS_SMEM);

    init_kernel<<<416, 256>>>(ctr0, ctr1, ctr2);
    pass1_kernel<<<dim3(64, NIMG), 256>>>(cls0, cls1, cls2);
    select1_kernel<<<NIMG*3, 256>>>();
    fb_hist_kernel<<<dim3(64, NIMG), 256>>>(cls0, cls1, cls2);
    fb_select_kernel<<<NIMG*3, 256>>>();
    xcutF_kernel<<<256, 256>>>();
    collect_kernel<<<dim3(64, NIMG), 256>>>(cls0, cls1, cls2);
    seg_select_kernel<<<NIMG*3, 256>>>(reg0, reg1, reg2, loc0, loc1, loc2);
    nms_kernel<<<NIMG, 1024, NMS_SMEM>>>(out);
}